// round 2
// baseline (speedup 1.0000x reference)
#include <cuda_runtime.h>
#include <cuda_bf16.h>
#include <math.h>

#define N_NODES 50000
#define N_EDGES 400000
#define MAX_DIM 512

// ---------------- scratch (static device globals; no allocs) ----------------
__device__ int   g_is64;                  // 1 if edge_index is int64, 0 if int32
__device__ int   g_cnt[N_NODES];          // in-degree (excluding self loop)
__device__ int   g_off[N_NODES + 1];      // CSR offsets
__device__ int   g_cur[N_NODES];          // fill cursors
__device__ int   g_srcs[N_EDGES];         // CSR column (src) indices
__device__ float g_dinv[N_NODES];         // D^{-1/2}
__device__ float g_buf0[(size_t)N_NODES * MAX_DIM];
__device__ float g_buf1[(size_t)N_NODES * MAX_DIM];

// ---------------- dtype detection ----------------
// Reads only the first 2KB (safe under both int32 and int64 layouts).
// If the buffer is int64, every 8-byte word is a valid node id < N_NODES.
// If it's int32, the high half of each word is an adjacent node id (≠0 almost
// surely), so the int64 interpretation blows past N_NODES.
__global__ void detect_kernel(const void* eiv) {
    const long long* p = (const long long*)eiv;
    int ok = 1;
    for (int e = 0; e < 256; ++e) {
        long long v = p[e];
        if (v < 0 || v >= N_NODES) { ok = 0; break; }
    }
    g_is64 = ok;
}

__device__ __forceinline__ int load_src(const void* eiv, int E, int e) {
    return g_is64 ? (int)((const long long*)eiv)[e] : ((const int*)eiv)[e];
}
__device__ __forceinline__ int load_dst(const void* eiv, int E, int e) {
    return g_is64 ? (int)((const long long*)eiv)[E + e] : ((const int*)eiv)[E + e];
}

// ---------------- preprocessing ----------------
__global__ void zero_cnt_kernel(int* cnt, int n) {
    int i = blockIdx.x * blockDim.x + threadIdx.x;
    if (i < n) cnt[i] = 0;
}

__global__ void count_kernel(const void* __restrict__ eiv, int* cnt, int E) {
    int e = blockIdx.x * blockDim.x + threadIdx.x;
    if (e < E) atomicAdd(&cnt[load_dst(eiv, E, e)], 1);
}

// single-block exclusive scan over 50000 counts; also writes dinv and cursor copy
__global__ void scan_kernel(const int* __restrict__ cnt, int* __restrict__ off,
                            int* __restrict__ cur, float* __restrict__ dinv, int n) {
    __shared__ int partial[1024];
    int tid = threadIdx.x;
    int chunk = (n + 1023) / 1024;
    int begin = tid * chunk;
    int end = begin + chunk; if (end > n) end = n; if (begin > n) begin = n;
    int sum = 0;
    for (int i = begin; i < end; ++i) sum += cnt[i];
    partial[tid] = sum;
    __syncthreads();
    for (int d = 1; d < 1024; d <<= 1) {
        int v = 0;
        if (tid >= d) v = partial[tid - d];
        __syncthreads();
        if (tid >= d) partial[tid] += v;
        __syncthreads();
    }
    int prefix = (tid == 0) ? 0 : partial[tid - 1];
    for (int i = begin; i < end; ++i) {
        off[i] = prefix;
        cur[i] = prefix;
        dinv[i] = rsqrtf((float)(cnt[i] + 1));   // +1 = self loop
        prefix += cnt[i];
    }
    if (tid == 1023) off[n] = partial[1023];
}

__global__ void fill_kernel(const void* __restrict__ eiv, int* cur,
                            int* __restrict__ srcs, int E) {
    int e = blockIdx.x * blockDim.x + threadIdx.x;
    if (e < E) {
        int d = load_dst(eiv, E, e);
        int pos = atomicAdd(&cur[d], 1);
        srcs[pos] = load_src(eiv, E, e);
    }
}

// per-node insertion sort: makes CSR (and thus float sums) deterministic
__global__ void sortseg_kernel(const int* __restrict__ off, int* __restrict__ srcs, int n) {
    int i = blockIdx.x * blockDim.x + threadIdx.x;
    if (i >= n) return;
    int s0 = off[i], s1 = off[i + 1];
    for (int a = s0 + 1; a < s1; ++a) {
        int key = srcs[a];
        int b = a - 1;
        while (b >= s0 && srcs[b] > key) { srcs[b + 1] = srcs[b]; --b; }
        srcs[b + 1] = key;
    }
}

// ---------------- aggregation: out[i] = dinv[i]*(dinv[i]*h[i] + sum dinv[s]*h[s]) ----------------
// block per node, thread per feature (dim in {64,128,256})
__global__ void agg_kernel(const float* __restrict__ H, float* __restrict__ Out,
                           const float* __restrict__ bias,
                           const int* __restrict__ off, const int* __restrict__ srcs,
                           const float* __restrict__ dinv,
                           int dim, int doRelu) {
    __shared__ int   s_src[64];
    __shared__ float s_w[64];
    int i = blockIdx.x;
    int f = threadIdx.x;
    float di = dinv[i];
    float acc = di * H[(size_t)i * dim + f];
    float acc2 = 0.0f;
    int s0 = off[i], s1 = off[i + 1];
    for (int base = s0; base < s1; base += 64) {
        int nb = s1 - base; if (nb > 64) nb = 64;
        __syncthreads();
        if (f < nb) { int s = srcs[base + f]; s_src[f] = s; s_w[f] = dinv[s]; }
        __syncthreads();
        int e = 0;
        for (; e + 1 < nb; e += 2) {
            acc  = fmaf(s_w[e],     H[(size_t)s_src[e]     * dim + f], acc);
            acc2 = fmaf(s_w[e + 1], H[(size_t)s_src[e + 1] * dim + f], acc2);
        }
        if (e < nb)
            acc = fmaf(s_w[e], H[(size_t)s_src[e] * dim + f], acc);
    }
    float v = di * (acc + acc2);
    if (bias) v += bias[f];
    if (doRelu) v = fmaxf(v, 0.0f);
    Out[(size_t)i * dim + f] = v;
}

// ---------------- SGEMM: C[M,N] = A[M,K] @ B[K,N] (+bias, +relu) ----------------
// BM=128, BN=64, BK=16, 256 threads, each computes 8x4
#define GBM 128
#define GBN 64
#define GBK 16
__global__ __launch_bounds__(256) void sgemm_kernel(
    const float* __restrict__ A, const float* __restrict__ B,
    const float* __restrict__ bias, float* __restrict__ C,
    int M, int K, int N, int doRelu) {
    __shared__ float As[GBK][GBM];
    __shared__ float Bs[GBK][GBN];
    int tid = threadIdx.x;
    int block_row = blockIdx.y * GBM;
    int block_col = blockIdx.x * GBN;

    int tcol = (tid & 15) * 4;   // 0..60
    int trow = (tid >> 4) * 8;   // 0..120

    float acc[8][4];
    #pragma unroll
    for (int i = 0; i < 8; ++i)
        #pragma unroll
        for (int j = 0; j < 4; ++j) acc[i][j] = 0.0f;

    int a_row0 = tid >> 2;       // 0..63
    int a_vc   = tid & 3;        // 0..3 (float4 columns)
    int b_row  = tid >> 4;       // 0..15
    int b_vc   = tid & 15;       // 0..15

    for (int k0 = 0; k0 < K; k0 += GBK) {
        #pragma unroll
        for (int h = 0; h < 2; ++h) {
            int r = a_row0 + h * 64;
            int gr = block_row + r;
            float4 v = make_float4(0.f, 0.f, 0.f, 0.f);
            if (gr < M) v = *(const float4*)&A[(size_t)gr * K + k0 + a_vc * 4];
            As[a_vc * 4 + 0][r] = v.x;
            As[a_vc * 4 + 1][r] = v.y;
            As[a_vc * 4 + 2][r] = v.z;
            As[a_vc * 4 + 3][r] = v.w;
        }
        {
            float4 v = *(const float4*)&B[(size_t)(k0 + b_row) * N + block_col + b_vc * 4];
            *(float4*)&Bs[b_row][b_vc * 4] = v;
        }
        __syncthreads();
        #pragma unroll
        for (int k = 0; k < GBK; ++k) {
            float ra[8], rb[4];
            #pragma unroll
            for (int i = 0; i < 8; ++i) ra[i] = As[k][trow + i];
            #pragma unroll
            for (int j = 0; j < 4; ++j) rb[j] = Bs[k][tcol + j];
            #pragma unroll
            for (int i = 0; i < 8; ++i)
                #pragma unroll
                for (int j = 0; j < 4; ++j)
                    acc[i][j] = fmaf(ra[i], rb[j], acc[i][j]);
        }
        __syncthreads();
    }
    float bb[4];
    #pragma unroll
    for (int j = 0; j < 4; ++j) bb[j] = bias ? bias[block_col + tcol + j] : 0.0f;
    #pragma unroll
    for (int i = 0; i < 8; ++i) {
        int gr = block_row + trow + i;
        if (gr < M) {
            #pragma unroll
            for (int j = 0; j < 4; ++j) {
                float v = acc[i][j] + bb[j];
                if (doRelu) v = fmaxf(v, 0.0f);
                C[(size_t)gr * N + block_col + tcol + j] = v;
            }
        }
    }
}

// ---------------- last-layer small GEMM: [N,64] @ [64,2] ----------------
__global__ void gemm64x2_kernel(const float* __restrict__ H, const float* __restrict__ W,
                                float* __restrict__ T, int n) {
    __shared__ float w[128];
    if (threadIdx.x < 128) w[threadIdx.x] = W[threadIdx.x];
    __syncthreads();
    int i = blockIdx.x * blockDim.x + threadIdx.x;
    if (i >= n) return;
    const float* h = H + (size_t)i * 64;
    float a0 = 0.f, a1 = 0.f;
    #pragma unroll
    for (int k = 0; k < 64; ++k) {
        float x = h[k];
        a0 = fmaf(x, w[2 * k], a0);
        a1 = fmaf(x, w[2 * k + 1], a1);
    }
    T[2 * i] = a0;
    T[2 * i + 1] = a1;
}

// ---------------- final aggregation (dim 2) + bias + log_softmax ----------------
__global__ void agg2_lsm_kernel(const float* __restrict__ T, const float* __restrict__ b,
                                float* __restrict__ out,
                                const int* __restrict__ off, const int* __restrict__ srcs,
                                const float* __restrict__ dinv, int n) {
    int i = blockIdx.x * blockDim.x + threadIdx.x;
    if (i >= n) return;
    float di = dinv[i];
    float a0 = di * T[2 * i];
    float a1 = di * T[2 * i + 1];
    int s0 = off[i], s1 = off[i + 1];
    for (int e = s0; e < s1; ++e) {
        int s = srcs[e];
        float w = dinv[s];
        a0 = fmaf(w, T[2 * s], a0);
        a1 = fmaf(w, T[2 * s + 1], a1);
    }
    float z0 = fmaf(di, a0, b[0]);
    float z1 = fmaf(di, a1, b[1]);
    float m = fmaxf(z0, z1);
    float lse = m + logf(expf(z0 - m) + expf(z1 - m));
    out[2 * i] = z0 - lse;
    out[2 * i + 1] = z1 - lse;
}

// ---------------- host launch ----------------
extern "C" void kernel_launch(void* const* d_in, const int* in_sizes, int n_in,
                              void* d_out, int out_size) {
    const float* x  = (const float*)d_in[0];
    const void*  ei = d_in[1];
    const float* W1 = (const float*)d_in[2];  const float* b1 = (const float*)d_in[3];
    const float* W2 = (const float*)d_in[4];  const float* b2 = (const float*)d_in[5];
    const float* W3 = (const float*)d_in[6];  const float* b3 = (const float*)d_in[7];
    const float* W4 = (const float*)d_in[8];  const float* b4 = (const float*)d_in[9];
    const float* W5 = (const float*)d_in[10]; const float* b5 = (const float*)d_in[11];
    float* out = (float*)d_out;

    const int N = N_NODES;
    const int E = N_EDGES;

    int *cnt, *off, *cur, *srcs;
    float *dinv, *buf0, *buf1;
    cudaGetSymbolAddress((void**)&cnt,  g_cnt);
    cudaGetSymbolAddress((void**)&off,  g_off);
    cudaGetSymbolAddress((void**)&cur,  g_cur);
    cudaGetSymbolAddress((void**)&srcs, g_srcs);
    cudaGetSymbolAddress((void**)&dinv, g_dinv);
    cudaGetSymbolAddress((void**)&buf0, g_buf0);
    cudaGetSymbolAddress((void**)&buf1, g_buf1);

    // ---- graph preprocessing (captured; re-run each replay) ----
    detect_kernel<<<1, 1>>>(ei);
    zero_cnt_kernel<<<(N + 255) / 256, 256>>>(cnt, N);
    count_kernel<<<(E + 255) / 256, 256>>>(ei, cnt, E);
    scan_kernel<<<1, 1024>>>(cnt, off, cur, dinv, N);
    fill_kernel<<<(E + 255) / 256, 256>>>(ei, cur, srcs, E);
    sortseg_kernel<<<(N + 255) / 256, 256>>>(off, srcs, N);

    dim3 blk(256);
    int mtiles = (N + GBM - 1) / GBM;  // 391

    // L1: agg(x,128) -> buf0 ; gemm(buf0@W1)+b1+relu -> buf1 [N,256]
    agg_kernel<<<N, 128>>>(x, buf0, nullptr, off, srcs, dinv, 128, 0);
    sgemm_kernel<<<dim3(256 / GBN, mtiles), blk>>>(buf0, W1, b1, buf1, N, 128, 256, 1);

    // L2: agg(buf1,256) -> buf0 ; gemm(@W2)+b2+relu -> buf1 [N,512]
    agg_kernel<<<N, 256>>>(buf1, buf0, nullptr, off, srcs, dinv, 256, 0);
    sgemm_kernel<<<dim3(512 / GBN, mtiles), blk>>>(buf0, W2, b2, buf1, N, 256, 512, 1);

    // L3: gemm(buf1@W3) -> buf0 [N,256] ; agg+b3+relu -> buf1
    sgemm_kernel<<<dim3(256 / GBN, mtiles), blk>>>(buf1, W3, nullptr, buf0, N, 512, 256, 0);
    agg_kernel<<<N, 256>>>(buf0, buf1, b3, off, srcs, dinv, 256, 1);

    // L4: gemm(buf1@W4) -> buf0 [N,64] ; agg+b4+relu -> buf1
    sgemm_kernel<<<dim3(64 / GBN, mtiles), blk>>>(buf1, W4, nullptr, buf0, N, 256, 64, 0);
    agg_kernel<<<N, 64>>>(buf0, buf1, b4, off, srcs, dinv, 64, 1);

    // L5: gemm(buf1@W5) -> buf0 [N,2] ; agg+b5 ; log_softmax -> out
    gemm64x2_kernel<<<(N + 127) / 128, 128>>>(buf1, W5, buf0, N);
    agg2_lsm_kernel<<<(N + 255) / 256, 256>>>(buf0, b5, out, off, srcs, dinv, N);
}

// round 3
// speedup vs baseline: 1.1160x; 1.1160x over previous
#include <cuda_runtime.h>
#include <cuda_bf16.h>
#include <math.h>

#define N_NODES 50000
#define N_EDGES 400000
#define MAX_DIM 512
#define SCAN_BLK 256
#define SCAN_NB ((N_NODES + SCAN_BLK - 1) / SCAN_BLK)   // 196

// ---------------- scratch (static device globals; no allocs) ----------------
__device__ int   g_is64;                  // 1 if edge_index is int64, 0 if int32
__device__ int   g_cnt[N_NODES];          // in-degree (excluding self loop)
__device__ int   g_off[N_NODES + 1];      // CSR offsets
__device__ int   g_cur[N_NODES];          // fill cursors
__device__ int   g_srcs[N_EDGES];         // CSR column (src) indices
__device__ int   g_bsum[SCAN_BLK];        // per-block sums for scan
__device__ float g_dinv[N_NODES];         // D^{-1/2}
__device__ float g_buf0[(size_t)N_NODES * MAX_DIM];
__device__ float g_buf1[(size_t)N_NODES * MAX_DIM];

// ---------------- f32x2 helpers ----------------
__device__ __forceinline__ unsigned long long pack2(float x) {
    unsigned long long r;
    asm("mov.b64 %0, {%1, %1};" : "=l"(r) : "f"(x));
    return r;
}
__device__ __forceinline__ void fma2(unsigned long long& d, unsigned long long a,
                                     unsigned long long b) {
    asm("fma.rn.f32x2 %0, %1, %2, %0;" : "+l"(d) : "l"(a), "l"(b));
}
__device__ __forceinline__ void unpack2(unsigned long long v, float& lo, float& hi) {
    asm("mov.b64 {%0, %1}, %2;" : "=f"(lo), "=f"(hi) : "l"(v));
}

// ---------------- dtype detection ----------------
__global__ void detect_kernel(const void* eiv) {
    const long long* p = (const long long*)eiv;
    int ok = 1;
    for (int e = 0; e < 256; ++e) {
        long long v = p[e];
        if (v < 0 || v >= N_NODES) { ok = 0; break; }
    }
    g_is64 = ok;
}

__device__ __forceinline__ int load_src(const void* eiv, int E, int e) {
    return g_is64 ? (int)((const long long*)eiv)[e] : ((const int*)eiv)[e];
}
__device__ __forceinline__ int load_dst(const void* eiv, int E, int e) {
    return g_is64 ? (int)((const long long*)eiv)[E + e] : ((const int*)eiv)[E + e];
}

// ---------------- preprocessing ----------------
__global__ void zero_cnt_kernel(int* cnt, int n) {
    int i = blockIdx.x * blockDim.x + threadIdx.x;
    if (i < n) cnt[i] = 0;
}

__global__ void count_kernel(const void* __restrict__ eiv, int* cnt, int E) {
    int e = blockIdx.x * blockDim.x + threadIdx.x;
    if (e < E) atomicAdd(&cnt[load_dst(eiv, E, e)], 1);
}

// phase 1: per-block exclusive scan + block sums
__global__ void scan1_kernel(const int* __restrict__ cnt, int* __restrict__ off,
                             int* __restrict__ bsum, int n) {
    __shared__ int sh[SCAN_BLK];
    int t = threadIdx.x;
    int i = blockIdx.x * SCAN_BLK + t;
    int v = (i < n) ? cnt[i] : 0;
    sh[t] = v;
    __syncthreads();
    for (int d = 1; d < SCAN_BLK; d <<= 1) {
        int x = 0;
        if (t >= d) x = sh[t - d];
        __syncthreads();
        if (t >= d) sh[t] += x;
        __syncthreads();
    }
    if (i < n) off[i] = sh[t] - v;          // exclusive within block
    if (t == SCAN_BLK - 1) bsum[blockIdx.x] = sh[t];
}

// phase 2: single-block scan of block sums; writes grand total to off[n]
__global__ void scan2_kernel(int* __restrict__ bsum, int* __restrict__ off, int nb, int n) {
    __shared__ int sh[SCAN_BLK];
    int t = threadIdx.x;
    int v = (t < nb) ? bsum[t] : 0;
    sh[t] = v;
    __syncthreads();
    for (int d = 1; d < SCAN_BLK; d <<= 1) {
        int x = 0;
        if (t >= d) x = sh[t - d];
        __syncthreads();
        if (t >= d) sh[t] += x;
        __syncthreads();
    }
    if (t < nb) bsum[t] = sh[t] - v;        // exclusive block prefix
    if (t == nb - 1) off[n] = sh[t];        // total
}

// phase 3: add block prefixes, write cursors and dinv
__global__ void scan3_kernel(const int* __restrict__ cnt, int* __restrict__ off,
                             int* __restrict__ cur, float* __restrict__ dinv,
                             const int* __restrict__ bsum, int n) {
    int i = blockIdx.x * blockDim.x + threadIdx.x;
    if (i < n) {
        int o = off[i] + bsum[i >> 8];
        off[i] = o;
        cur[i] = o;
        dinv[i] = rsqrtf((float)(cnt[i] + 1));
    }
}

__global__ void fill_kernel(const void* __restrict__ eiv, int* cur,
                            int* __restrict__ srcs, int E) {
    int e = blockIdx.x * blockDim.x + threadIdx.x;
    if (e < E) {
        int d = load_dst(eiv, E, e);
        int pos = atomicAdd(&cur[d], 1);
        srcs[pos] = load_src(eiv, E, e);
    }
}

// per-node insertion sort: makes CSR (and thus float sums) deterministic
__global__ void sortseg_kernel(const int* __restrict__ off, int* __restrict__ srcs, int n) {
    int i = blockIdx.x * blockDim.x + threadIdx.x;
    if (i >= n) return;
    int s0 = off[i], s1 = off[i + 1];
    for (int a = s0 + 1; a < s1; ++a) {
        int key = srcs[a];
        int b = a - 1;
        while (b >= s0 && srcs[b] > key) { srcs[b + 1] = srcs[b]; --b; }
        srcs[b + 1] = key;
    }
}

// ---------------- aggregation: out[i] = dinv[i]*(dinv[i]*h[i] + sum dinv[s]*h[s]) ----------------
__global__ void agg_kernel(const float* __restrict__ H, float* __restrict__ Out,
                           const float* __restrict__ bias,
                           const int* __restrict__ off, const int* __restrict__ srcs,
                           const float* __restrict__ dinv,
                           int dim, int doRelu) {
    __shared__ int   s_src[64];
    __shared__ float s_w[64];
    int i = blockIdx.x;
    int f = threadIdx.x;
    float di = dinv[i];
    float acc = di * H[(size_t)i * dim + f];
    float acc2 = 0.0f;
    int s0 = off[i], s1 = off[i + 1];
    for (int base = s0; base < s1; base += 64) {
        int nb = s1 - base; if (nb > 64) nb = 64;
        __syncthreads();
        if (f < nb) { int s = srcs[base + f]; s_src[f] = s; s_w[f] = dinv[s]; }
        __syncthreads();
        int e = 0;
        for (; e + 1 < nb; e += 2) {
            acc  = fmaf(s_w[e],     H[(size_t)s_src[e]     * dim + f], acc);
            acc2 = fmaf(s_w[e + 1], H[(size_t)s_src[e + 1] * dim + f], acc2);
        }
        if (e < nb)
            acc = fmaf(s_w[e], H[(size_t)s_src[e] * dim + f], acc);
    }
    float v = di * (acc + acc2);
    if (bias) v += bias[f];
    if (doRelu) v = fmaxf(v, 0.0f);
    Out[(size_t)i * dim + f] = v;
}

// ---------------- SGEMM with packed f32x2 FMA ----------------
// BM=128, BN=64, BK=16, 256 threads, each computes 8 rows x 4 cols (2 f32x2 pairs)
#define GBM 128
#define GBN 64
#define GBK 16
__global__ __launch_bounds__(256) void sgemm_kernel(
    const float* __restrict__ A, const float* __restrict__ B,
    const float* __restrict__ bias, float* __restrict__ C,
    int M, int K, int N, int doRelu) {
    __shared__ float As[GBK][GBM];
    __shared__ float Bs[GBK][GBN];
    int tid = threadIdx.x;
    int block_row = blockIdx.y * GBM;
    int block_col = blockIdx.x * GBN;

    int tcol = (tid & 15) * 4;   // 0..60
    int trow = (tid >> 4) * 8;   // 0..120

    unsigned long long acc[8][2];
    #pragma unroll
    for (int i = 0; i < 8; ++i) { acc[i][0] = 0ull; acc[i][1] = 0ull; }

    int a_row0 = tid >> 2;       // 0..63
    int a_vc   = tid & 3;        // 0..3 (float4 columns)
    int b_row  = tid >> 4;       // 0..15
    int b_vc   = tid & 15;       // 0..15

    for (int k0 = 0; k0 < K; k0 += GBK) {
        #pragma unroll
        for (int h = 0; h < 2; ++h) {
            int r = a_row0 + h * 64;
            int gr = block_row + r;
            float4 v = make_float4(0.f, 0.f, 0.f, 0.f);
            if (gr < M) v = *(const float4*)&A[(size_t)gr * K + k0 + a_vc * 4];
            As[a_vc * 4 + 0][r] = v.x;
            As[a_vc * 4 + 1][r] = v.y;
            As[a_vc * 4 + 2][r] = v.z;
            As[a_vc * 4 + 3][r] = v.w;
        }
        {
            float4 v = *(const float4*)&B[(size_t)(k0 + b_row) * N + block_col + b_vc * 4];
            *(float4*)&Bs[b_row][b_vc * 4] = v;
        }
        __syncthreads();
        #pragma unroll
        for (int k = 0; k < GBK; ++k) {
            unsigned long long rb0 = *(const unsigned long long*)&Bs[k][tcol];
            unsigned long long rb1 = *(const unsigned long long*)&Bs[k][tcol + 2];
            float ra[8];
            #pragma unroll
            for (int i = 0; i < 8; ++i) ra[i] = As[k][trow + i];
            #pragma unroll
            for (int i = 0; i < 8; ++i) {
                unsigned long long rap = pack2(ra[i]);
                fma2(acc[i][0], rap, rb0);
                fma2(acc[i][1], rap, rb1);
            }
        }
        __syncthreads();
    }
    float bb[4];
    #pragma unroll
    for (int j = 0; j < 4; ++j) bb[j] = bias ? bias[block_col + tcol + j] : 0.0f;
    #pragma unroll
    for (int i = 0; i < 8; ++i) {
        int gr = block_row + trow + i;
        if (gr < M) {
            float c[4];
            unpack2(acc[i][0], c[0], c[1]);
            unpack2(acc[i][1], c[2], c[3]);
            #pragma unroll
            for (int j = 0; j < 4; ++j) {
                float v = c[j] + bb[j];
                if (doRelu) v = fmaxf(v, 0.0f);
                C[(size_t)gr * N + block_col + tcol + j] = v;
            }
        }
    }
}

// ---------------- last-layer small GEMM: [N,64] @ [64,2] ----------------
__global__ void gemm64x2_kernel(const float* __restrict__ H, const float* __restrict__ W,
                                float* __restrict__ T, int n) {
    __shared__ float w[128];
    if (threadIdx.x < 128) w[threadIdx.x] = W[threadIdx.x];
    __syncthreads();
    int i = blockIdx.x * blockDim.x + threadIdx.x;
    if (i >= n) return;
    const float* h = H + (size_t)i * 64;
    unsigned long long acc = 0ull;
    #pragma unroll
    for (int k = 0; k < 64; ++k) {
        unsigned long long wv = *(const unsigned long long*)&w[2 * k];
        fma2(acc, pack2(h[k]), wv);
    }
    float a0, a1;
    unpack2(acc, a0, a1);
    T[2 * i] = a0;
    T[2 * i + 1] = a1;
}

// ---------------- final aggregation (dim 2) + bias + log_softmax ----------------
__global__ void agg2_lsm_kernel(const float* __restrict__ T, const float* __restrict__ b,
                                float* __restrict__ out,
                                const int* __restrict__ off, const int* __restrict__ srcs,
                                const float* __restrict__ dinv, int n) {
    int i = blockIdx.x * blockDim.x + threadIdx.x;
    if (i >= n) return;
    float di = dinv[i];
    float a0 = di * T[2 * i];
    float a1 = di * T[2 * i + 1];
    int s0 = off[i], s1 = off[i + 1];
    for (int e = s0; e < s1; ++e) {
        int s = srcs[e];
        float w = dinv[s];
        a0 = fmaf(w, T[2 * s], a0);
        a1 = fmaf(w, T[2 * s + 1], a1);
    }
    float z0 = fmaf(di, a0, b[0]);
    float z1 = fmaf(di, a1, b[1]);
    float m = fmaxf(z0, z1);
    float lse = m + logf(expf(z0 - m) + expf(z1 - m));
    out[2 * i] = z0 - lse;
    out[2 * i + 1] = z1 - lse;
}

// ---------------- host launch ----------------
extern "C" void kernel_launch(void* const* d_in, const int* in_sizes, int n_in,
                              void* d_out, int out_size) {
    const float* x  = (const float*)d_in[0];
    const void*  ei = d_in[1];
    const float* W1 = (const float*)d_in[2];  const float* b1 = (const float*)d_in[3];
    const float* W2 = (const float*)d_in[4];  const float* b2 = (const float*)d_in[5];
    const float* W3 = (const float*)d_in[6];  const float* b3 = (const float*)d_in[7];
    const float* W4 = (const float*)d_in[8];  const float* b4 = (const float*)d_in[9];
    const float* W5 = (const float*)d_in[10]; const float* b5 = (const float*)d_in[11];
    float* out = (float*)d_out;

    const int N = N_NODES;
    const int E = N_EDGES;

    int *cnt, *off, *cur, *srcs, *bsum;
    float *dinv, *buf0, *buf1;
    cudaGetSymbolAddress((void**)&cnt,  g_cnt);
    cudaGetSymbolAddress((void**)&off,  g_off);
    cudaGetSymbolAddress((void**)&cur,  g_cur);
    cudaGetSymbolAddress((void**)&srcs, g_srcs);
    cudaGetSymbolAddress((void**)&bsum, g_bsum);
    cudaGetSymbolAddress((void**)&dinv, g_dinv);
    cudaGetSymbolAddress((void**)&buf0, g_buf0);
    cudaGetSymbolAddress((void**)&buf1, g_buf1);

    // ---- graph preprocessing (captured; re-run each replay) ----
    detect_kernel<<<1, 1>>>(ei);
    zero_cnt_kernel<<<(N + 255) / 256, 256>>>(cnt, N);
    count_kernel<<<(E + 255) / 256, 256>>>(ei, cnt, E);
    scan1_kernel<<<SCAN_NB, SCAN_BLK>>>(cnt, off, bsum, N);
    scan2_kernel<<<1, SCAN_BLK>>>(bsum, off, SCAN_NB, N);
    scan3_kernel<<<(N + 255) / 256, 256>>>(cnt, off, cur, dinv, bsum, N);
    fill_kernel<<<(E + 255) / 256, 256>>>(ei, cur, srcs, E);
    sortseg_kernel<<<(N + 255) / 256, 256>>>(off, srcs, N);

    dim3 blk(256);
    int mtiles = (N + GBM - 1) / GBM;  // 391

    // L1: agg(x,128) -> buf0 ; gemm(buf0@W1)+b1+relu -> buf1 [N,256]
    agg_kernel<<<N, 128>>>(x, buf0, nullptr, off, srcs, dinv, 128, 0);
    sgemm_kernel<<<dim3(256 / GBN, mtiles), blk>>>(buf0, W1, b1, buf1, N, 128, 256, 1);

    // L2: agg(buf1,256) -> buf0 ; gemm(@W2)+b2+relu -> buf1 [N,512]
    agg_kernel<<<N, 256>>>(buf1, buf0, nullptr, off, srcs, dinv, 256, 0);
    sgemm_kernel<<<dim3(512 / GBN, mtiles), blk>>>(buf0, W2, b2, buf1, N, 256, 512, 1);

    // L3: gemm(buf1@W3) -> buf0 [N,256] ; agg+b3+relu -> buf1
    sgemm_kernel<<<dim3(256 / GBN, mtiles), blk>>>(buf1, W3, nullptr, buf0, N, 512, 256, 0);
    agg_kernel<<<N, 256>>>(buf0, buf1, b3, off, srcs, dinv, 256, 1);

    // L4: gemm(buf1@W4) -> buf0 [N,64] ; agg+b4+relu -> buf1
    sgemm_kernel<<<dim3(64 / GBN, mtiles), blk>>>(buf1, W4, nullptr, buf0, N, 256, 64, 0);
    agg_kernel<<<N, 64>>>(buf0, buf1, b4, off, srcs, dinv, 64, 1);

    // L5: gemm(buf1@W5) -> buf0 [N,2] ; agg+b5 ; log_softmax -> out
    gemm64x2_kernel<<<(N + 127) / 128, 128>>>(buf1, W5, buf0, N);
    agg2_lsm_kernel<<<(N + 255) / 256, 256>>>(buf0, b5, out, off, srcs, dinv, N);
}

// round 5
// speedup vs baseline: 1.6271x; 1.4580x over previous
#include <cuda_runtime.h>
#include <cuda_bf16.h>
#include <mma.h>
#include <math.h>
#include <stdint.h>

using namespace nvcuda;

#define N_NODES 50000
#define N_EDGES 400000
#define MT_COUNT 392                 // padded row tiles: 392*128 = 50176
#define PAD_ROWS (MT_COUNT * 128)
#define SCAN_BLK 256
#define SCAN_NB ((N_NODES + SCAN_BLK - 1) / SCAN_BLK)

typedef unsigned int u32;
typedef unsigned long long u64;

// ---------------- scratch (static device globals; no allocs) ----------------
__device__ int   g_is64;
__device__ int   g_cnt[N_NODES];
__device__ int   g_off[N_NODES + 1];
__device__ int   g_cur[N_NODES];
__device__ int   g_srcs[N_EDGES];
__device__ int   g_bsum[SCAN_BLK];
__device__ float g_dinv[N_NODES];
__device__ float g_buf0[(size_t)N_NODES * 512];
__device__ float g_buf1[(size_t)N_NODES * 512];
// A-operand bf16 hi/lo row-major buffers (two ping-pong sets)
__device__ __nv_bfloat16 g_ah0[(size_t)PAD_ROWS * 512];
__device__ __nv_bfloat16 g_al0[(size_t)PAD_ROWS * 512];
__device__ __nv_bfloat16 g_ah1[(size_t)PAD_ROWS * 512];
__device__ __nv_bfloat16 g_al1[(size_t)PAD_ROWS * 512];
// B-operand bf16 hi/lo row-major [K,N]
__device__ __nv_bfloat16 g_bh[262144];
__device__ __nv_bfloat16 g_bl[262144];

// ---------------- helpers ----------------
__device__ __forceinline__ u32 smem_u32(const void* p) {
    return (u32)__cvta_generic_to_shared(p);
}
__device__ __forceinline__ void cp_async16(u32 dst, const void* src) {
    asm volatile("cp.async.cg.shared.global [%0], [%1], 16;" :: "r"(dst), "l"(src));
}
__device__ __forceinline__ void cp_commit() {
    asm volatile("cp.async.commit_group;" ::: "memory");
}
template <int N>
__device__ __forceinline__ void cp_wait() {
    asm volatile("cp.async.wait_group %0;" :: "n"(N) : "memory");
}

// ---------------- edge dtype detection ----------------
__global__ void detect_kernel(const void* eiv) {
    const long long* p = (const long long*)eiv;
    int ok = 1;
    for (int e = 0; e < 256; ++e) {
        long long v = p[e];
        if (v < 0 || v >= N_NODES) { ok = 0; break; }
    }
    g_is64 = ok;
}
__device__ __forceinline__ int load_src(const void* eiv, int E, int e) {
    return g_is64 ? (int)((const long long*)eiv)[e] : ((const int*)eiv)[e];
}
__device__ __forceinline__ int load_dst(const void* eiv, int E, int e) {
    return g_is64 ? (int)((const long long*)eiv)[E + e] : ((const int*)eiv)[E + e];
}

// ---------------- preprocessing ----------------
__global__ void zero_cnt_kernel(int* cnt, int n) {
    int i = blockIdx.x * blockDim.x + threadIdx.x;
    if (i < n) cnt[i] = 0;
}
__global__ void count_kernel(const void* __restrict__ eiv, int* cnt, int E) {
    int e = blockIdx.x * blockDim.x + threadIdx.x;
    if (e < E) atomicAdd(&cnt[load_dst(eiv, E, e)], 1);
}
__global__ void scan1_kernel(const int* __restrict__ cnt, int* __restrict__ off,
                             int* __restrict__ bsum, int n) {
    __shared__ int sh[SCAN_BLK];
    int t = threadIdx.x;
    int i = blockIdx.x * SCAN_BLK + t;
    int v = (i < n) ? cnt[i] : 0;
    sh[t] = v;
    __syncthreads();
    for (int d = 1; d < SCAN_BLK; d <<= 1) {
        int x = 0;
        if (t >= d) x = sh[t - d];
        __syncthreads();
        if (t >= d) sh[t] += x;
        __syncthreads();
    }
    if (i < n) off[i] = sh[t] - v;
    if (t == SCAN_BLK - 1) bsum[blockIdx.x] = sh[t];
}
__global__ void scan2_kernel(int* __restrict__ bsum, int* __restrict__ off, int nb, int n) {
    __shared__ int sh[SCAN_BLK];
    int t = threadIdx.x;
    int v = (t < nb) ? bsum[t] : 0;
    sh[t] = v;
    __syncthreads();
    for (int d = 1; d < SCAN_BLK; d <<= 1) {
        int x = 0;
        if (t >= d) x = sh[t - d];
        __syncthreads();
        if (t >= d) sh[t] += x;
        __syncthreads();
    }
    if (t < nb) bsum[t] = sh[t] - v;
    if (t == nb - 1) off[n] = sh[t];
}
__global__ void scan3_kernel(const int* __restrict__ cnt, int* __restrict__ off,
                             int* __restrict__ cur, float* __restrict__ dinv,
                             const int* __restrict__ bsum, int n) {
    int i = blockIdx.x * blockDim.x + threadIdx.x;
    if (i < n) {
        int o = off[i] + bsum[i >> 8];
        off[i] = o;
        cur[i] = o;
        dinv[i] = rsqrtf((float)(cnt[i] + 1));
    }
}
__global__ void fill_kernel(const void* __restrict__ eiv, int* cur,
                            int* __restrict__ srcs, int E) {
    int e = blockIdx.x * blockDim.x + threadIdx.x;
    if (e < E) {
        int d = load_dst(eiv, E, e);
        int pos = atomicAdd(&cur[d], 1);
        srcs[pos] = load_src(eiv, E, e);
    }
}
__global__ void sortseg_kernel(const int* __restrict__ off, int* __restrict__ srcs, int n) {
    int i = blockIdx.x * blockDim.x + threadIdx.x;
    if (i >= n) return;
    int s0 = off[i], s1 = off[i + 1];
    for (int a = s0 + 1; a < s1; ++a) {
        int key = srcs[a];
        int b = a - 1;
        while (b >= s0 && srcs[b] > key) { srcs[b + 1] = srcs[b]; --b; }
        srcs[b + 1] = key;
    }
}

// ---------------- aggregation ----------------
// out[i] = dinv[i]*(dinv[i]*h[i] + sum dinv[s]*h[s]) (+bias, relu)
// One block per (padded) node; threads = D/2, each a float2 feature pair.
// Output: fp32 rows OR bf16 hi/lo row-major [PAD][D] (zeros for padding rows).
__global__ void agg_kernel(const float* __restrict__ H,
                           const int* __restrict__ off, const int* __restrict__ srcs,
                           const float* __restrict__ dinv,
                           const float* __restrict__ bias, int doRelu, int D,
                           float* __restrict__ outRows,
                           __nv_bfloat16* __restrict__ Oh, __nv_bfloat16* __restrict__ Ol) {
    __shared__ int   s_src[128];
    __shared__ float s_w[128];
    int i = blockIdx.x;
    int t = threadIdx.x;
    int T = blockDim.x;
    int f0 = 2 * t;
    float v0 = 0.0f, v1 = 0.0f;
    if (i < N_NODES) {
        float di = dinv[i];
        float2 h = ((const float2*)(H + (size_t)i * D))[t];
        float a0 = di * h.x, a1 = di * h.y;
        float b0 = 0.0f, b1 = 0.0f;
        int s0 = off[i], s1 = off[i + 1];
        for (int base = s0; base < s1; base += T) {
            int nb = s1 - base; if (nb > T) nb = T;
            __syncthreads();
            if (t < nb) { int s = srcs[base + t]; s_src[t] = s; s_w[t] = dinv[s]; }
            __syncthreads();
            int e = 0;
            for (; e + 1 < nb; e += 2) {
                float2 x = ((const float2*)(H + (size_t)s_src[e] * D))[t];
                float2 y = ((const float2*)(H + (size_t)s_src[e + 1] * D))[t];
                a0 = fmaf(s_w[e], x.x, a0);
                a1 = fmaf(s_w[e], x.y, a1);
                b0 = fmaf(s_w[e + 1], y.x, b0);
                b1 = fmaf(s_w[e + 1], y.y, b1);
            }
            if (e < nb) {
                float2 x = ((const float2*)(H + (size_t)s_src[e] * D))[t];
                a0 = fmaf(s_w[e], x.x, a0);
                a1 = fmaf(s_w[e], x.y, a1);
            }
        }
        v0 = di * (a0 + b0);
        v1 = di * (a1 + b1);
        if (bias) { v0 += bias[f0]; v1 += bias[f0 + 1]; }
        if (doRelu) { v0 = fmaxf(v0, 0.0f); v1 = fmaxf(v1, 0.0f); }
    }
    if (outRows) {
        if (i < N_NODES) {
            float2 o; o.x = v0; o.y = v1;
            ((float2*)(outRows + (size_t)i * D))[t] = o;
        }
    } else {
        __nv_bfloat16 h0 = __float2bfloat16(v0);
        __nv_bfloat16 h1 = __float2bfloat16(v1);
        __nv_bfloat16 l0 = __float2bfloat16(v0 - __bfloat162float(h0));
        __nv_bfloat16 l1 = __float2bfloat16(v1 - __bfloat162float(h1));
        __nv_bfloat162 hp; hp.x = h0; hp.y = h1;
        __nv_bfloat162 lp; lp.x = l0; lp.y = l1;
        size_t base = (size_t)i * D + f0;
        *(__nv_bfloat162*)(Oh + base) = hp;
        *(__nv_bfloat162*)(Ol + base) = lp;
    }
}

// ---------------- weight decomposition: W[K,N] fp32 -> Bh/Bl row-major bf16 ----------------
__global__ void decompW_kernel(const float* __restrict__ W,
                               __nv_bfloat16* __restrict__ Bh, __nv_bfloat16* __restrict__ Bl,
                               int total) {
    int e = blockIdx.x * blockDim.x + threadIdx.x;
    if (e >= total) return;
    float v = W[e];
    __nv_bfloat16 h = __float2bfloat16(v);
    __nv_bfloat16 l = __float2bfloat16(v - __bfloat162float(h));
    Bh[e] = h;
    Bl[e] = l;
}

// ---------------- WMMA bf16x3 GEMM ----------------
// C[128, BN] per CTA; K' = 3K via segments (Ah,Bh), (Al,Bh), (Ah,Bl).
// 256 threads = 8 warps; warp computes 32 x (BN/2) via 16x16x16 frags.
template <int BN>
__global__ __launch_bounds__(256) void gemm_wmma_kernel(
    const __nv_bfloat16* __restrict__ Ah, const __nv_bfloat16* __restrict__ Al,
    const __nv_bfloat16* __restrict__ Bh, const __nv_bfloat16* __restrict__ Bl,
    const float* __restrict__ bias, int doRelu,
    float* __restrict__ outRows, int outN,
    __nv_bfloat16* __restrict__ Oh, __nv_bfloat16* __restrict__ Ol, int outK,
    int K, int N) {
    constexpr int A_LD = 40;            // 32 + 8 pad (halves)
    constexpr int B_LD = BN + 8;
    constexpr int A_BYTES = 128 * A_LD * 2;
    constexpr int B_BYTES = 32 * B_LD * 2;
    constexpr int STAGE = A_BYTES + B_BYTES;
    constexpr int WN = BN / 2;          // warp col span (64 or 32)
    constexpr int NF = WN / 16;         // n-frags per warp

    extern __shared__ char sm[];
    int tid = threadIdx.x;
    int wid = tid >> 5;
    int mt = blockIdx.x, nt = blockIdx.y;
    int row0 = mt * 128, bn0 = nt * BN;
    int KT = K >> 5;
    int total = 3 * KT;

    auto As = [&](int s) { return (__nv_bfloat16*)(sm + s * STAGE); };
    auto Bs = [&](int s) { return (__nv_bfloat16*)(sm + s * STAGE + A_BYTES); };

    auto issue = [&](int u, int s) {
        int seg = (u < KT) ? 0 : ((u < 2 * KT) ? 1 : 2);
        int k0 = (u - seg * KT) << 5;
        const __nv_bfloat16* Asrc = (seg == 1) ? Al : Ah;
        const __nv_bfloat16* Bsrc = (seg == 2) ? Bl : Bh;
        // A: 128x32 halves = 512 x 16B chunks, 2 per thread
        #pragma unroll
        for (int c = 0; c < 2; ++c) {
            int chunk = tid + c * 256;
            int row = chunk >> 2, col8 = (chunk & 3) * 8;
            u32 dst = smem_u32(As(s) + row * A_LD + col8);
            cp_async16(dst, Asrc + (size_t)(row0 + row) * K + k0 + col8);
        }
        // B: 32xBN halves
        constexpr int NCB = 32 * BN / 8 / 256;  // 2 (BN=128) or 1 (BN=64)
        #pragma unroll
        for (int c = 0; c < NCB; ++c) {
            int chunk = tid + c * 256;
            int r = chunk / (BN / 8), c8 = (chunk % (BN / 8)) * 8;
            u32 dst = smem_u32(Bs(s) + r * B_LD + c8);
            cp_async16(dst, Bsrc + (size_t)(k0 + r) * N + bn0 + c8);
        }
        cp_commit();
    };

    int wm = (wid & 3) * 32;
    int wn = (wid >> 2) * WN;

    wmma::fragment<wmma::accumulator, 16, 16, 16, float> acc[2][NF];
    #pragma unroll
    for (int mi = 0; mi < 2; ++mi)
        #pragma unroll
        for (int ni = 0; ni < NF; ++ni) wmma::fill_fragment(acc[mi][ni], 0.0f);

    issue(0, 0);
    for (int u = 0; u < total; ++u) {
        if (u + 1 < total) {
            issue(u + 1, (u + 1) & 1);
            cp_wait<1>();
        } else {
            cp_wait<0>();
        }
        __syncthreads();
        int s = u & 1;
        const __nv_bfloat16* a = As(s);
        const __nv_bfloat16* b = Bs(s);
        #pragma unroll
        for (int kf = 0; kf < 2; ++kf) {
            wmma::fragment<wmma::matrix_a, 16, 16, 16, __nv_bfloat16, wmma::row_major> af[2];
            wmma::fragment<wmma::matrix_b, 16, 16, 16, __nv_bfloat16, wmma::row_major> bf[NF];
            #pragma unroll
            for (int mi = 0; mi < 2; ++mi)
                wmma::load_matrix_sync(af[mi], a + (wm + mi * 16) * A_LD + kf * 16, A_LD);
            #pragma unroll
            for (int ni = 0; ni < NF; ++ni)
                wmma::load_matrix_sync(bf[ni], b + (kf * 16) * B_LD + wn + ni * 16, B_LD);
            #pragma unroll
            for (int mi = 0; mi < 2; ++mi)
                #pragma unroll
                for (int ni = 0; ni < NF; ++ni)
                    wmma::mma_sync(acc[mi][ni], af[mi], bf[ni], acc[mi][ni]);
        }
        __syncthreads();
    }

    // epilogue via smem
    float* Cs = (float*)sm;
    #pragma unroll
    for (int mi = 0; mi < 2; ++mi)
        #pragma unroll
        for (int ni = 0; ni < NF; ++ni)
            wmma::store_matrix_sync(Cs + (wm + mi * 16) * BN + wn + ni * 16,
                                    acc[mi][ni], BN, wmma::mem_row_major);
    __syncthreads();

    for (int idx = tid; idx < 128 * BN; idx += 256) {
        int r = idx / BN, c = idx % BN;
        float v = Cs[idx];
        if (bias) v += bias[bn0 + c];
        if (doRelu) v = fmaxf(v, 0.0f);
        int m = row0 + r;
        if (outRows) {
            if (m < N_NODES) outRows[(size_t)m * outN + bn0 + c] = v;
        } else {
            __nv_bfloat16 h = __float2bfloat16(v);
            __nv_bfloat16 l = __float2bfloat16(v - __bfloat162float(h));
            size_t base = (size_t)m * outK + bn0 + c;
            Oh[base] = h;
            Ol[base] = l;
        }
    }
}

// ---------------- last-layer small GEMM: [N,64] @ [64,2] ----------------
__global__ void gemm64x2_kernel(const float* __restrict__ H, const float* __restrict__ W,
                                float* __restrict__ T, int n) {
    __shared__ float w[128];
    if (threadIdx.x < 128) w[threadIdx.x] = W[threadIdx.x];
    __syncthreads();
    int i = blockIdx.x * blockDim.x + threadIdx.x;
    if (i >= n) return;
    const float* h = H + (size_t)i * 64;
    float a0 = 0.f, a1 = 0.f;
    #pragma unroll
    for (int k = 0; k < 64; ++k) {
        float x = h[k];
        a0 = fmaf(x, w[2 * k], a0);
        a1 = fmaf(x, w[2 * k + 1], a1);
    }
    T[2 * i] = a0;
    T[2 * i + 1] = a1;
}

// ---------------- final aggregation (dim 2) + bias + log_softmax ----------------
__global__ void agg2_lsm_kernel(const float* __restrict__ T, const float* __restrict__ b,
                                float* __restrict__ out,
                                const int* __restrict__ off, const int* __restrict__ srcs,
                                const float* __restrict__ dinv, int n) {
    int i = blockIdx.x * blockDim.x + threadIdx.x;
    if (i >= n) return;
    float di = dinv[i];
    float a0 = di * T[2 * i];
    float a1 = di * T[2 * i + 1];
    int s0 = off[i], s1 = off[i + 1];
    for (int e = s0; e < s1; ++e) {
        int s = srcs[e];
        float w = dinv[s];
        a0 = fmaf(w, T[2 * s], a0);
        a1 = fmaf(w, T[2 * s + 1], a1);
    }
    float z0 = fmaf(di, a0, b[0]);
    float z1 = fmaf(di, a1, b[1]);
    float m = fmaxf(z0, z1);
    float lse = m + logf(expf(z0 - m) + expf(z1 - m));
    out[2 * i] = z0 - lse;
    out[2 * i + 1] = z1 - lse;
}

// ---------------- host launch ----------------
extern "C" void kernel_launch(void* const* d_in, const int* in_sizes, int n_in,
                              void* d_out, int out_size) {
    const float* x  = (const float*)d_in[0];
    const void*  ei = d_in[1];
    const float* W1 = (const float*)d_in[2];  const float* b1 = (const float*)d_in[3];
    const float* W2 = (const float*)d_in[4];  const float* b2 = (const float*)d_in[5];
    const float* W3 = (const float*)d_in[6];  const float* b3 = (const float*)d_in[7];
    const float* W4 = (const float*)d_in[8];  const float* b4 = (const float*)d_in[9];
    const float* W5 = (const float*)d_in[10]; const float* b5 = (const float*)d_in[11];
    float* out = (float*)d_out;

    const int N = N_NODES;
    const int E = N_EDGES;

    int *cnt, *off, *cur, *srcs, *bsum;
    float *dinv, *buf0, *buf1;
    __nv_bfloat16 *ah0, *al0, *ah1, *al1, *bh, *bl;
    cudaGetSymbolAddress((void**)&cnt,  g_cnt);
    cudaGetSymbolAddress((void**)&off,  g_off);
    cudaGetSymbolAddress((void**)&cur,  g_cur);
    cudaGetSymbolAddress((void**)&srcs, g_srcs);
    cudaGetSymbolAddress((void**)&bsum, g_bsum);
    cudaGetSymbolAddress((void**)&dinv, g_dinv);
    cudaGetSymbolAddress((void**)&buf0, g_buf0);
    cudaGetSymbolAddress((void**)&buf1, g_buf1);
    cudaGetSymbolAddress((void**)&ah0,  g_ah0);
    cudaGetSymbolAddress((void**)&al0,  g_al0);
    cudaGetSymbolAddress((void**)&ah1,  g_ah1);
    cudaGetSymbolAddress((void**)&al1,  g_al1);
    cudaGetSymbolAddress((void**)&bh,   g_bh);
    cudaGetSymbolAddress((void**)&bl,   g_bl);

    const int SMEM128 = 128 * 128 * 4;  // 65536 (epilogue dominates)
    const int SMEM64  = 128 * 64 * 4;   // 32768
    static int s_attr_done = 0;
    cudaFuncSetAttribute(gemm_wmma_kernel<128>, cudaFuncAttributeMaxDynamicSharedMemorySize, SMEM128);
    cudaFuncSetAttribute(gemm_wmma_kernel<64>,  cudaFuncAttributeMaxDynamicSharedMemorySize, SMEM64);
    (void)s_attr_done;

    // ---- graph preprocessing ----
    detect_kernel<<<1, 1>>>(ei);
    zero_cnt_kernel<<<(N + 255) / 256, 256>>>(cnt, N);
    count_kernel<<<(E + 255) / 256, 256>>>(ei, cnt, E);
    scan1_kernel<<<SCAN_NB, SCAN_BLK>>>(cnt, off, bsum, N);
    scan2_kernel<<<1, SCAN_BLK>>>(bsum, off, SCAN_NB, N);
    scan3_kernel<<<(N + 255) / 256, 256>>>(cnt, off, cur, dinv, bsum, N);
    fill_kernel<<<(E + 255) / 256, 256>>>(ei, cur, srcs, E);
    sortseg_kernel<<<(N + 255) / 256, 256>>>(off, srcs, N);

    // L1: agg(x, D=128) -> hi/lo set0 ; gemm K=128 N=256 +b1+relu -> rows buf0
    agg_kernel<<<PAD_ROWS, 64>>>(x, off, srcs, dinv, nullptr, 0, 128, nullptr, ah0, al0);
    decompW_kernel<<<(128 * 256 + 255) / 256, 256>>>(W1, bh, bl, 128 * 256);
    gemm_wmma_kernel<128><<<dim3(MT_COUNT, 2), 256, SMEM128>>>(
        ah0, al0, bh, bl, b1, 1, buf0, 256, nullptr, nullptr, 0, 128, 256);

    // L2: agg(buf0, D=256) -> hi/lo set0 ; gemm K=256 N=512 +b2+relu -> hi/lo set1
    agg_kernel<<<PAD_ROWS, 128>>>(buf0, off, srcs, dinv, nullptr, 0, 256, nullptr, ah0, al0);
    decompW_kernel<<<(256 * 512 + 255) / 256, 256>>>(W2, bh, bl, 256 * 512);
    gemm_wmma_kernel<128><<<dim3(MT_COUNT, 4), 256, SMEM128>>>(
        ah0, al0, bh, bl, b2, 1, nullptr, 0, ah1, al1, 512, 256, 512);

    // L3: gemm K=512 N=256 -> rows buf1 ; agg(+b3+relu) -> hi/lo set0
    decompW_kernel<<<(512 * 256 + 255) / 256, 256>>>(W3, bh, bl, 512 * 256);
    gemm_wmma_kernel<128><<<dim3(MT_COUNT, 2), 256, SMEM128>>>(
        ah1, al1, bh, bl, nullptr, 0, buf1, 256, nullptr, nullptr, 0, 512, 256);
    agg_kernel<<<PAD_ROWS, 128>>>(buf1, off, srcs, dinv, b3, 1, 256, nullptr, ah0, al0);

    // L4: gemm K=256 N=64 -> rows buf0 ; agg(+b4+relu) -> rows buf1 (D=64)
    decompW_kernel<<<(256 * 64 + 255) / 256, 256>>>(W4, bh, bl, 256 * 64);
    gemm_wmma_kernel<64><<<dim3(MT_COUNT, 1), 256, SMEM64>>>(
        ah0, al0, bh, bl, nullptr, 0, buf0, 64, nullptr, nullptr, 0, 256, 64);
    agg_kernel<<<N, 32>>>(buf0, off, srcs, dinv, b4, 1, 64, buf1, nullptr, nullptr);

    // L5: gemm [N,64]@[64,2] -> buf0 ; agg(dim2) + b5 + log_softmax -> out
    gemm64x2_kernel<<<(N + 127) / 128, 128>>>(buf1, W5, buf0, N);
    agg2_lsm_kernel<<<(N + 255) / 256, 256>>>(buf0, b5, out, off, srcs, dinv, N);
}

// round 6
// speedup vs baseline: 2.2482x; 1.3817x over previous
#include <cuda_runtime.h>
#include <cuda_fp16.h>
#include <mma.h>
#include <math.h>
#include <stdint.h>

using namespace nvcuda;

#define N_NODES 50000
#define N_EDGES 400000
#define MT_COUNT 392                 // padded row tiles: 392*128 = 50176
#define PAD_ROWS (MT_COUNT * 128)
#define SCAN_BLK 256
#define SCAN_NB ((N_NODES + SCAN_BLK - 1) / SCAN_BLK)

typedef unsigned int u32;
typedef unsigned long long u64;

// ---------------- scratch (static device globals; no allocs) ----------------
__device__ int   g_is64;
__device__ int   g_cnt[N_NODES];
__device__ int   g_off[N_NODES + 1];
__device__ int   g_cur[N_NODES];
__device__ int   g_srcs[N_EDGES];
__device__ int   g_bsum[SCAN_BLK];
__device__ float g_dinv[N_NODES];
__device__ float g_buf0[(size_t)N_NODES * 512];
__device__ float g_buf1[(size_t)N_NODES * 512];
// A-operand fp16 hi/lo row-major buffers (two ping-pong sets)
__device__ __half g_ah0[(size_t)PAD_ROWS * 512];
__device__ __half g_al0[(size_t)PAD_ROWS * 512];
__device__ __half g_ah1[(size_t)PAD_ROWS * 512];
__device__ __half g_al1[(size_t)PAD_ROWS * 512];
// B-operand fp16 row-major [K,N]
__device__ __half g_bh[262144];

// ---------------- helpers ----------------
__device__ __forceinline__ u32 smem_u32(const void* p) {
    return (u32)__cvta_generic_to_shared(p);
}
__device__ __forceinline__ void cp_async16(u32 dst, const void* src) {
    asm volatile("cp.async.cg.shared.global [%0], [%1], 16;" :: "r"(dst), "l"(src));
}
__device__ __forceinline__ void cp_commit() {
    asm volatile("cp.async.commit_group;" ::: "memory");
}
template <int N>
__device__ __forceinline__ void cp_wait() {
    asm volatile("cp.async.wait_group %0;" :: "n"(N) : "memory");
}
__device__ __forceinline__ void split_f32(float v, __half& h, __half& l) {
    h = __float2half(v);
    l = __float2half(v - __half2float(h));
}

// ---------------- edge dtype detection (warp-parallel) ----------------
__global__ void detect_kernel(const void* eiv) {
    const long long* p = (const long long*)eiv;
    int t = threadIdx.x;
    int bad = 0;
    #pragma unroll
    for (int e = t; e < 256; e += 32) {
        long long v = p[e];
        if (v < 0 || v >= N_NODES) bad = 1;
    }
    unsigned m = __ballot_sync(0xFFFFFFFFu, bad);
    if (t == 0) g_is64 = (m == 0u);
}
__device__ __forceinline__ int load_src(const void* eiv, int E, int e) {
    return g_is64 ? (int)((const long long*)eiv)[e] : ((const int*)eiv)[e];
}
__device__ __forceinline__ int load_dst(const void* eiv, int E, int e) {
    return g_is64 ? (int)((const long long*)eiv)[E + e] : ((const int*)eiv)[E + e];
}

// ---------------- preprocessing ----------------
__global__ void zero_cnt_kernel(int* cnt, int n) {
    int i = blockIdx.x * blockDim.x + threadIdx.x;
    if (i < n) cnt[i] = 0;
}
__global__ void count_kernel(const void* __restrict__ eiv, int* cnt, int E) {
    int e = blockIdx.x * blockDim.x + threadIdx.x;
    if (e < E) atomicAdd(&cnt[load_dst(eiv, E, e)], 1);
}
__global__ void scan1_kernel(const int* __restrict__ cnt, int* __restrict__ off,
                             int* __restrict__ bsum, int n) {
    __shared__ int sh[SCAN_BLK];
    int t = threadIdx.x;
    int i = blockIdx.x * SCAN_BLK + t;
    int v = (i < n) ? cnt[i] : 0;
    sh[t] = v;
    __syncthreads();
    for (int d = 1; d < SCAN_BLK; d <<= 1) {
        int x = 0;
        if (t >= d) x = sh[t - d];
        __syncthreads();
        if (t >= d) sh[t] += x;
        __syncthreads();
    }
    if (i < n) off[i] = sh[t] - v;
    if (t == SCAN_BLK - 1) bsum[blockIdx.x] = sh[t];
}
__global__ void scan2_kernel(int* __restrict__ bsum, int* __restrict__ off, int nb, int n) {
    __shared__ int sh[SCAN_BLK];
    int t = threadIdx.x;
    int v = (t < nb) ? bsum[t] : 0;
    sh[t] = v;
    __syncthreads();
    for (int d = 1; d < SCAN_BLK; d <<= 1) {
        int x = 0;
        if (t >= d) x = sh[t - d];
        __syncthreads();
        if (t >= d) sh[t] += x;
        __syncthreads();
    }
    if (t < nb) bsum[t] = sh[t] - v;
    if (t == nb - 1) off[n] = sh[t];
}
__global__ void scan3_kernel(const int* __restrict__ cnt, int* __restrict__ off,
                             int* __restrict__ cur, float* __restrict__ dinv,
                             const int* __restrict__ bsum, int n) {
    int i = blockIdx.x * blockDim.x + threadIdx.x;
    if (i < n) {
        int o = off[i] + bsum[i >> 8];
        off[i] = o;
        cur[i] = o;
        dinv[i] = rsqrtf((float)(cnt[i] + 1));
    }
}
__global__ void fill_kernel(const void* __restrict__ eiv, int* cur,
                            int* __restrict__ srcs, int E) {
    int e = blockIdx.x * blockDim.x + threadIdx.x;
    if (e < E) {
        int d = load_dst(eiv, E, e);
        int pos = atomicAdd(&cur[d], 1);
        srcs[pos] = load_src(eiv, E, e);
    }
}
__global__ void sortseg_kernel(const int* __restrict__ off, int* __restrict__ srcs, int n) {
    int i = blockIdx.x * blockDim.x + threadIdx.x;
    if (i >= n) return;
    int s0 = off[i], s1 = off[i + 1];
    for (int a = s0 + 1; a < s1; ++a) {
        int key = srcs[a];
        int b = a - 1;
        while (b >= s0 && srcs[b] > key) { srcs[b + 1] = srcs[b]; --b; }
        srcs[b + 1] = key;
    }
}

// ---------------- aggregation ----------------
// out[i] = dinv[i]*(dinv[i]*h[i] + sum dinv[s]*h[s]) (+bias, relu)
// One block per (padded) node; threads = D/2, each a float2 feature pair.
// Output: fp32 rows OR fp16 hi/lo row-major [PAD][D] (zeros for padding rows).
__global__ void agg_kernel(const float* __restrict__ H,
                           const int* __restrict__ off, const int* __restrict__ srcs,
                           const float* __restrict__ dinv,
                           const float* __restrict__ bias, int doRelu, int D,
                           float* __restrict__ outRows,
                           __half* __restrict__ Oh, __half* __restrict__ Ol) {
    __shared__ int   s_src[128];
    __shared__ float s_w[128];
    int i = blockIdx.x;
    int t = threadIdx.x;
    int T = blockDim.x;
    int f0 = 2 * t;
    float v0 = 0.0f, v1 = 0.0f;
    if (i < N_NODES) {
        float di = dinv[i];
        float2 h = ((const float2*)(H + (size_t)i * D))[t];
        float a0 = di * h.x, a1 = di * h.y;
        float b0 = 0.0f, b1 = 0.0f;
        int s0 = off[i], s1 = off[i + 1];
        for (int base = s0; base < s1; base += T) {
            int nb = s1 - base; if (nb > T) nb = T;
            __syncthreads();
            if (t < nb) { int s = srcs[base + t]; s_src[t] = s; s_w[t] = dinv[s]; }
            __syncthreads();
            int e = 0;
            for (; e + 1 < nb; e += 2) {
                float2 x = ((const float2*)(H + (size_t)s_src[e] * D))[t];
                float2 y = ((const float2*)(H + (size_t)s_src[e + 1] * D))[t];
                a0 = fmaf(s_w[e], x.x, a0);
                a1 = fmaf(s_w[e], x.y, a1);
                b0 = fmaf(s_w[e + 1], y.x, b0);
                b1 = fmaf(s_w[e + 1], y.y, b1);
            }
            if (e < nb) {
                float2 x = ((const float2*)(H + (size_t)s_src[e] * D))[t];
                a0 = fmaf(s_w[e], x.x, a0);
                a1 = fmaf(s_w[e], x.y, a1);
            }
        }
        v0 = di * (a0 + b0);
        v1 = di * (a1 + b1);
        if (bias) { v0 += bias[f0]; v1 += bias[f0 + 1]; }
        if (doRelu) { v0 = fmaxf(v0, 0.0f); v1 = fmaxf(v1, 0.0f); }
    }
    if (outRows) {
        if (i < N_NODES) {
            float2 o; o.x = v0; o.y = v1;
            ((float2*)(outRows + (size_t)i * D))[t] = o;
        }
    } else {
        __half h0, l0, h1, l1;
        split_f32(v0, h0, l0);
        split_f32(v1, h1, l1);
        __half2 hp; hp.x = h0; hp.y = h1;
        __half2 lp; lp.x = l0; lp.y = l1;
        size_t base = (size_t)i * D + f0;
        *(__half2*)(Oh + base) = hp;
        *(__half2*)(Ol + base) = lp;
    }
}

// ---------------- weight conversion: W[K,N] fp32 -> fp16 ----------------
__global__ void decompW_kernel(const float* __restrict__ W,
                               __half* __restrict__ Bh, int total) {
    int e = blockIdx.x * blockDim.x + threadIdx.x;
    if (e >= total) return;
    Bh[e] = __float2half(W[e]);
}

// ---------------- WMMA fp16x2 GEMM ----------------
// C[128, BN] per CTA; K' = 2K via segments (Ah,Bh), (Al,Bh).
// 256 threads = 8 warps; warp computes 32 x (BN/2) via 16x16x16 frags.
template <int BN>
__global__ __launch_bounds__(256) void gemm_wmma_kernel(
    const __half* __restrict__ Ah, const __half* __restrict__ Al,
    const __half* __restrict__ Bh,
    const float* __restrict__ bias, int doRelu,
    float* __restrict__ outRows, int outN,
    __half* __restrict__ Oh, __half* __restrict__ Ol, int outK,
    int K, int N) {
    constexpr int A_LD = 40;            // 32 + 8 pad (halves)
    constexpr int B_LD = BN + 8;
    constexpr int A_BYTES = 128 * A_LD * 2;
    constexpr int B_BYTES = 32 * B_LD * 2;
    constexpr int STAGE = A_BYTES + B_BYTES;
    constexpr int WN = BN / 2;          // warp col span (64 or 32)
    constexpr int NF = WN / 16;         // n-frags per warp

    extern __shared__ char sm[];
    int tid = threadIdx.x;
    int wid = tid >> 5;
    int mt = blockIdx.x, nt = blockIdx.y;
    int row0 = mt * 128, bn0 = nt * BN;
    int KT = K >> 5;
    int total = 2 * KT;

    auto As = [&](int s) { return (__half*)(sm + s * STAGE); };
    auto Bs = [&](int s) { return (__half*)(sm + s * STAGE + A_BYTES); };

    auto issue = [&](int u, int s) {
        int seg = (u < KT) ? 0 : 1;
        int k0 = (u - seg * KT) << 5;
        const __half* Asrc = seg ? Al : Ah;
        // A: 128x32 halves = 512 x 16B chunks, 2 per thread
        #pragma unroll
        for (int c = 0; c < 2; ++c) {
            int chunk = tid + c * 256;
            int row = chunk >> 2, col8 = (chunk & 3) * 8;
            u32 dst = smem_u32(As(s) + row * A_LD + col8);
            cp_async16(dst, Asrc + (size_t)(row0 + row) * K + k0 + col8);
        }
        // B: 32xBN halves
        constexpr int NCB = 32 * BN / 8 / 256;  // 2 (BN=128) or 1 (BN=64)
        #pragma unroll
        for (int c = 0; c < NCB; ++c) {
            int chunk = tid + c * 256;
            int r = chunk / (BN / 8), c8 = (chunk % (BN / 8)) * 8;
            u32 dst = smem_u32(Bs(s) + r * B_LD + c8);
            cp_async16(dst, Bh + (size_t)(k0 + r) * N + bn0 + c8);
        }
        cp_commit();
    };

    int wm = (wid & 3) * 32;
    int wn = (wid >> 2) * WN;

    wmma::fragment<wmma::accumulator, 16, 16, 16, float> acc[2][NF];
    #pragma unroll
    for (int mi = 0; mi < 2; ++mi)
        #pragma unroll
        for (int ni = 0; ni < NF; ++ni) wmma::fill_fragment(acc[mi][ni], 0.0f);

    issue(0, 0);
    for (int u = 0; u < total; ++u) {
        if (u + 1 < total) {
            issue(u + 1, (u + 1) & 1);
            cp_wait<1>();
        } else {
            cp_wait<0>();
        }
        __syncthreads();
        int s = u & 1;
        const __half* a = As(s);
        const __half* b = Bs(s);
        #pragma unroll
        for (int kf = 0; kf < 2; ++kf) {
            wmma::fragment<wmma::matrix_a, 16, 16, 16, __half, wmma::row_major> af[2];
            wmma::fragment<wmma::matrix_b, 16, 16, 16, __half, wmma::row_major> bf[NF];
            #pragma unroll
            for (int mi = 0; mi < 2; ++mi)
                wmma::load_matrix_sync(af[mi], a + (wm + mi * 16) * A_LD + kf * 16, A_LD);
            #pragma unroll
            for (int ni = 0; ni < NF; ++ni)
                wmma::load_matrix_sync(bf[ni], b + (kf * 16) * B_LD + wn + ni * 16, B_LD);
            #pragma unroll
            for (int mi = 0; mi < 2; ++mi)
                #pragma unroll
                for (int ni = 0; ni < NF; ++ni)
                    wmma::mma_sync(acc[mi][ni], af[mi], bf[ni], acc[mi][ni]);
        }
        __syncthreads();
    }

    // epilogue via smem
    float* Cs = (float*)sm;
    #pragma unroll
    for (int mi = 0; mi < 2; ++mi)
        #pragma unroll
        for (int ni = 0; ni < NF; ++ni)
            wmma::store_matrix_sync(Cs + (wm + mi * 16) * BN + wn + ni * 16,
                                    acc[mi][ni], BN, wmma::mem_row_major);
    __syncthreads();

    for (int idx = tid; idx < 128 * BN; idx += 256) {
        int r = idx / BN, c = idx % BN;
        float v = Cs[idx];
        if (bias) v += bias[bn0 + c];
        if (doRelu) v = fmaxf(v, 0.0f);
        int m = row0 + r;
        if (outRows) {
            if (m < N_NODES) outRows[(size_t)m * outN + bn0 + c] = v;
        } else {
            __half h, l;
            split_f32(v, h, l);
            size_t base = (size_t)m * outK + bn0 + c;
            Oh[base] = h;
            Ol[base] = l;
        }
    }
}

// ---------------- last-layer small GEMM: [N,64] @ [64,2] ----------------
__global__ void gemm64x2_kernel(const float* __restrict__ H, const float* __restrict__ W,
                                float* __restrict__ T, int n) {
    __shared__ float w[128];
    if (threadIdx.x < 128) w[threadIdx.x] = W[threadIdx.x];
    __syncthreads();
    int i = blockIdx.x * blockDim.x + threadIdx.x;
    if (i >= n) return;
    const float* h = H + (size_t)i * 64;
    float a0 = 0.f, a1 = 0.f;
    #pragma unroll
    for (int k = 0; k < 64; ++k) {
        float x = h[k];
        a0 = fmaf(x, w[2 * k], a0);
        a1 = fmaf(x, w[2 * k + 1], a1);
    }
    T[2 * i] = a0;
    T[2 * i + 1] = a1;
}

// ---------------- final aggregation (dim 2) + bias + log_softmax ----------------
__global__ void agg2_lsm_kernel(const float* __restrict__ T, const float* __restrict__ b,
                                float* __restrict__ out,
                                const int* __restrict__ off, const int* __restrict__ srcs,
                                const float* __restrict__ dinv, int n) {
    int i = blockIdx.x * blockDim.x + threadIdx.x;
    if (i >= n) return;
    float di = dinv[i];
    float a0 = di * T[2 * i];
    float a1 = di * T[2 * i + 1];
    int s0 = off[i], s1 = off[i + 1];
    for (int e = s0; e < s1; ++e) {
        int s = srcs[e];
        float w = dinv[s];
        a0 = fmaf(w, T[2 * s], a0);
        a1 = fmaf(w, T[2 * s + 1], a1);
    }
    float z0 = fmaf(di, a0, b[0]);
    float z1 = fmaf(di, a1, b[1]);
    float m = fmaxf(z0, z1);
    float lse = m + logf(expf(z0 - m) + expf(z1 - m));
    out[2 * i] = z0 - lse;
    out[2 * i + 1] = z1 - lse;
}

// ---------------- host launch ----------------
extern "C" void kernel_launch(void* const* d_in, const int* in_sizes, int n_in,
                              void* d_out, int out_size) {
    const float* x  = (const float*)d_in[0];
    const void*  ei = d_in[1];
    const float* W1 = (const float*)d_in[2];  const float* b1 = (const float*)d_in[3];
    const float* W2 = (const float*)d_in[4];  const float* b2 = (const float*)d_in[5];
    const float* W3 = (const float*)d_in[6];  const float* b3 = (const float*)d_in[7];
    const float* W4 = (const float*)d_in[8];  const float* b4 = (const float*)d_in[9];
    const float* W5 = (const float*)d_in[10]; const float* b5 = (const float*)d_in[11];
    float* out = (float*)d_out;

    const int N = N_NODES;
    const int E = N_EDGES;

    int *cnt, *off, *cur, *srcs, *bsum;
    float *dinv, *buf0, *buf1;
    __half *ah0, *al0, *ah1, *al1, *bh;
    cudaGetSymbolAddress((void**)&cnt,  g_cnt);
    cudaGetSymbolAddress((void**)&off,  g_off);
    cudaGetSymbolAddress((void**)&cur,  g_cur);
    cudaGetSymbolAddress((void**)&srcs, g_srcs);
    cudaGetSymbolAddress((void**)&bsum, g_bsum);
    cudaGetSymbolAddress((void**)&dinv, g_dinv);
    cudaGetSymbolAddress((void**)&buf0, g_buf0);
    cudaGetSymbolAddress((void**)&buf1, g_buf1);
    cudaGetSymbolAddress((void**)&ah0,  g_ah0);
    cudaGetSymbolAddress((void**)&al0,  g_al0);
    cudaGetSymbolAddress((void**)&ah1,  g_ah1);
    cudaGetSymbolAddress((void**)&al1,  g_al1);
    cudaGetSymbolAddress((void**)&bh,   g_bh);

    const int SMEM128 = 128 * 128 * 4;  // 65536 (epilogue dominates)
    const int SMEM64  = 128 * 64 * 4;   // 32768
    cudaFuncSetAttribute(gemm_wmma_kernel<128>, cudaFuncAttributeMaxDynamicSharedMemorySize, SMEM128);
    cudaFuncSetAttribute(gemm_wmma_kernel<64>,  cudaFuncAttributeMaxDynamicSharedMemorySize, SMEM64);

    // ---- graph preprocessing ----
    detect_kernel<<<1, 32>>>(ei);
    zero_cnt_kernel<<<(N + 255) / 256, 256>>>(cnt, N);
    count_kernel<<<(E + 255) / 256, 256>>>(ei, cnt, E);
    scan1_kernel<<<SCAN_NB, SCAN_BLK>>>(cnt, off, bsum, N);
    scan2_kernel<<<1, SCAN_BLK>>>(bsum, off, SCAN_NB, N);
    scan3_kernel<<<(N + 255) / 256, 256>>>(cnt, off, cur, dinv, bsum, N);
    fill_kernel<<<(E + 255) / 256, 256>>>(ei, cur, srcs, E);
    sortseg_kernel<<<(N + 255) / 256, 256>>>(off, srcs, N);

    // L1: agg(x, D=128) -> hi/lo set0 ; gemm K=128 N=256 +b1+relu -> rows buf0
    agg_kernel<<<PAD_ROWS, 64>>>(x, off, srcs, dinv, nullptr, 0, 128, nullptr, ah0, al0);
    decompW_kernel<<<(128 * 256 + 255) / 256, 256>>>(W1, bh, 128 * 256);
    gemm_wmma_kernel<128><<<dim3(MT_COUNT, 2), 256, SMEM128>>>(
        ah0, al0, bh, b1, 1, buf0, 256, nullptr, nullptr, 0, 128, 256);

    // L2: agg(buf0, D=256) -> hi/lo set0 ; gemm K=256 N=512 +b2+relu -> hi/lo set1
    agg_kernel<<<PAD_ROWS, 128>>>(buf0, off, srcs, dinv, nullptr, 0, 256, nullptr, ah0, al0);
    decompW_kernel<<<(256 * 512 + 255) / 256, 256>>>(W2, bh, 256 * 512);
    gemm_wmma_kernel<128><<<dim3(MT_COUNT, 4), 256, SMEM128>>>(
        ah0, al0, bh, b2, 1, nullptr, 0, ah1, al1, 512, 256, 512);

    // L3: gemm K=512 N=256 -> rows buf1 ; agg(+b3+relu) -> hi/lo set0
    decompW_kernel<<<(512 * 256 + 255) / 256, 256>>>(W3, bh, 512 * 256);
    gemm_wmma_kernel<128><<<dim3(MT_COUNT, 2), 256, SMEM128>>>(
        ah1, al1, bh, nullptr, 0, buf1, 256, nullptr, nullptr, 0, 512, 256);
    agg_kernel<<<PAD_ROWS, 128>>>(buf1, off, srcs, dinv, b3, 1, 256, nullptr, ah0, al0);

    // L4: gemm K=256 N=64 -> rows buf0 ; agg(+b4+relu) -> rows buf1 (D=64)
    decompW_kernel<<<(256 * 64 + 255) / 256, 256>>>(W4, bh, 256 * 64);
    gemm_wmma_kernel<64><<<dim3(MT_COUNT, 1), 256, SMEM64>>>(
        ah0, al0, bh, nullptr, 0, buf0, 64, nullptr, nullptr, 0, 256, 64);
    agg_kernel<<<N, 32>>>(buf0, off, srcs, dinv, b4, 1, 64, buf1, nullptr, nullptr);

    // L5: gemm [N,64]@[64,2] -> buf0 ; agg(dim2) + b5 + log_softmax -> out
    gemm64x2_kernel<<<(N + 127) / 128, 128>>>(buf1, W5, buf0, N);
    agg2_lsm_kernel<<<(N + 255) / 256, 256>>>(buf0, b5, out, off, srcs, dinv, N);
}

// round 7
// speedup vs baseline: 2.3135x; 1.0291x over previous
#include <cuda_runtime.h>
#include <cuda_fp16.h>
#include <mma.h>
#include <math.h>
#include <stdint.h>

using namespace nvcuda;

#define N_NODES 50000
#define N_EDGES 400000
#define MT_COUNT 392                 // padded row tiles: 392*128 = 50176
#define PAD_ROWS (MT_COUNT * 128)
#define SCAN_BLK 256
#define SCAN_NB ((N_NODES + SCAN_BLK - 1) / SCAN_BLK)

typedef unsigned int u32;
typedef unsigned long long u64;

// ---------------- scratch (static device globals; no allocs) ----------------
__device__ int   g_is64;
__device__ int   g_cnt[N_NODES];
__device__ int   g_off[N_NODES + 1];
__device__ int   g_cur[N_NODES];
__device__ int   g_srcs[N_EDGES];
__device__ int   g_bsum[SCAN_BLK];
__device__ float g_dinv[N_NODES];
__device__ float g_buf0[(size_t)N_NODES * 512];
__device__ float g_buf1[(size_t)N_NODES * 512];
// A-operand fp16 hi/lo row-major buffers (two ping-pong sets)
__device__ __half g_ah0[(size_t)PAD_ROWS * 512];
__device__ __half g_al0[(size_t)PAD_ROWS * 512];
__device__ __half g_ah1[(size_t)PAD_ROWS * 512];
__device__ __half g_al1[(size_t)PAD_ROWS * 512];
// B-operand fp16 row-major [K,N], one buffer per layer
__device__ __half g_b1[128 * 256];
__device__ __half g_b2[256 * 512];
__device__ __half g_b3[512 * 256];
__device__ __half g_b4[256 * 64];

// ---------------- helpers ----------------
__device__ __forceinline__ u32 smem_u32(const void* p) {
    return (u32)__cvta_generic_to_shared(p);
}
__device__ __forceinline__ void cp_async16(u32 dst, const void* src) {
    asm volatile("cp.async.cg.shared.global [%0], [%1], 16;" :: "r"(dst), "l"(src));
}
__device__ __forceinline__ void cp_commit() {
    asm volatile("cp.async.commit_group;" ::: "memory");
}
__device__ __forceinline__ void cp_wait_dyn(int n) {
    if (n <= 0)      asm volatile("cp.async.wait_group 0;" ::: "memory");
    else if (n == 1) asm volatile("cp.async.wait_group 1;" ::: "memory");
    else             asm volatile("cp.async.wait_group 2;" ::: "memory");
}
__device__ __forceinline__ void split_f32(float v, __half& h, __half& l) {
    h = __float2half(v);
    l = __float2half(v - __half2float(h));
}

// ---------------- edge dtype detection (warp-parallel) ----------------
__global__ void detect_kernel(const void* eiv) {
    const long long* p = (const long long*)eiv;
    int t = threadIdx.x;
    int bad = 0;
    #pragma unroll
    for (int e = t; e < 256; e += 32) {
        long long v = p[e];
        if (v < 0 || v >= N_NODES) bad = 1;
    }
    unsigned m = __ballot_sync(0xFFFFFFFFu, bad);
    if (t == 0) g_is64 = (m == 0u);
}
__device__ __forceinline__ int load_src(const void* eiv, int E, int e) {
    return g_is64 ? (int)((const long long*)eiv)[e] : ((const int*)eiv)[e];
}
__device__ __forceinline__ int load_dst(const void* eiv, int E, int e) {
    return g_is64 ? (int)((const long long*)eiv)[E + e] : ((const int*)eiv)[E + e];
}

// ---------------- preprocessing ----------------
__global__ void zero_cnt_kernel(int* cnt, int n) {
    int i = blockIdx.x * blockDim.x + threadIdx.x;
    if (i < n) cnt[i] = 0;
}
__global__ void count_kernel(const void* __restrict__ eiv, int* cnt, int E) {
    int e = blockIdx.x * blockDim.x + threadIdx.x;
    if (e < E) atomicAdd(&cnt[load_dst(eiv, E, e)], 1);
}
__global__ void scan1_kernel(const int* __restrict__ cnt, int* __restrict__ off,
                             int* __restrict__ bsum, int n) {
    __shared__ int sh[SCAN_BLK];
    int t = threadIdx.x;
    int i = blockIdx.x * SCAN_BLK + t;
    int v = (i < n) ? cnt[i] : 0;
    sh[t] = v;
    __syncthreads();
    for (int d = 1; d < SCAN_BLK; d <<= 1) {
        int x = 0;
        if (t >= d) x = sh[t - d];
        __syncthreads();
        if (t >= d) sh[t] += x;
        __syncthreads();
    }
    if (i < n) off[i] = sh[t] - v;
    if (t == SCAN_BLK - 1) bsum[blockIdx.x] = sh[t];
}
__global__ void scan2_kernel(int* __restrict__ bsum, int* __restrict__ off, int nb, int n) {
    __shared__ int sh[SCAN_BLK];
    int t = threadIdx.x;
    int v = (t < nb) ? bsum[t] : 0;
    sh[t] = v;
    __syncthreads();
    for (int d = 1; d < SCAN_BLK; d <<= 1) {
        int x = 0;
        if (t >= d) x = sh[t - d];
        __syncthreads();
        if (t >= d) sh[t] += x;
        __syncthreads();
    }
    if (t < nb) bsum[t] = sh[t] - v;
    if (t == nb - 1) off[n] = sh[t];
}
__global__ void scan3_kernel(const int* __restrict__ cnt, int* __restrict__ off,
                             int* __restrict__ cur, float* __restrict__ dinv,
                             const int* __restrict__ bsum, int n) {
    int i = blockIdx.x * blockDim.x + threadIdx.x;
    if (i < n) {
        int o = off[i] + bsum[i >> 8];
        off[i] = o;
        cur[i] = o;
        dinv[i] = rsqrtf((float)(cnt[i] + 1));
    }
}
__global__ void fill_kernel(const void* __restrict__ eiv, int* cur,
                            int* __restrict__ srcs, int E) {
    int e = blockIdx.x * blockDim.x + threadIdx.x;
    if (e < E) {
        int d = load_dst(eiv, E, e);
        int pos = atomicAdd(&cur[d], 1);
        srcs[pos] = load_src(eiv, E, e);
    }
}
__global__ void sortseg_kernel(const int* __restrict__ off, int* __restrict__ srcs, int n) {
    int i = blockIdx.x * blockDim.x + threadIdx.x;
    if (i >= n) return;
    int s0 = off[i], s1 = off[i + 1];
    for (int a = s0 + 1; a < s1; ++a) {
        int key = srcs[a];
        int b = a - 1;
        while (b >= s0 && srcs[b] > key) { srcs[b + 1] = srcs[b]; --b; }
        srcs[b + 1] = key;
    }
}

// ---------------- fused weight conversion W1..W4 -> fp16 ----------------
#define W1_SZ (128 * 256)
#define W2_SZ (256 * 512)
#define W3_SZ (512 * 256)
#define W4_SZ (256 * 64)
__global__ void decomp_all_kernel(const float* __restrict__ W1, const float* __restrict__ W2,
                                  const float* __restrict__ W3, const float* __restrict__ W4,
                                  __half* __restrict__ B1, __half* __restrict__ B2,
                                  __half* __restrict__ B3, __half* __restrict__ B4) {
    int e = blockIdx.x * blockDim.x + threadIdx.x;
    int total = W1_SZ + W2_SZ + W3_SZ + W4_SZ;
    if (e >= total) return;
    if (e < W1_SZ) { B1[e] = __float2half(W1[e]); return; }
    e -= W1_SZ;
    if (e < W2_SZ) { B2[e] = __float2half(W2[e]); return; }
    e -= W2_SZ;
    if (e < W3_SZ) { B3[e] = __float2half(W3[e]); return; }
    e -= W3_SZ;
    B4[e] = __float2half(W4[e]);
}

// ---------------- aggregation v2 ----------------
// out[i] = dinv[i]*(dinv[i]*h[i] + sum dinv[s]*h[s]) (+bias, relu)
// Block per (padded) node; T = D/EPT threads; EPT = 4 (float4) or 2 (float2).
// 4-edge unrolled gather. Output fp32 rows OR fp16 hi/lo (zeros for pad rows).
template <int EPT>
__global__ void agg_kernel(const float* __restrict__ H,
                           const int* __restrict__ off, const int* __restrict__ srcs,
                           const float* __restrict__ dinv,
                           const float* __restrict__ bias, int doRelu, int D,
                           float* __restrict__ outRows,
                           __half* __restrict__ Oh, __half* __restrict__ Ol) {
    __shared__ int   s_src[128];
    __shared__ float s_w[128];
    int i = blockIdx.x;
    int t = threadIdx.x;
    int T = blockDim.x;                 // D / EPT
    float vout[EPT];
    #pragma unroll
    for (int j = 0; j < EPT; ++j) vout[j] = 0.0f;

    if (i < N_NODES) {
        float di = dinv[i];
        float acc[4][EPT];
        // own row (scaled by di) into acc[0]
        {
            const float* rp = H + (size_t)i * D + t * EPT;
            if (EPT == 4) {
                float4 v = *(const float4*)rp;
                acc[0][0] = di * v.x; acc[0][1] = di * v.y;
                acc[0][2] = di * v.z; acc[0][3] = di * v.w;
            } else {
                float2 v = *(const float2*)rp;
                acc[0][0] = di * v.x; acc[0][1] = di * v.y;
            }
        }
        #pragma unroll
        for (int u = 1; u < 4; ++u)
            #pragma unroll
            for (int j = 0; j < EPT; ++j) acc[u][j] = 0.0f;

        int s0 = off[i], s1 = off[i + 1];
        for (int base = s0; base < s1; base += 128) {
            int nb = s1 - base; if (nb > 128) nb = 128;
            __syncthreads();
            for (int j = t; j < nb; j += T) {
                int s = srcs[base + j];
                s_src[j] = s;
                s_w[j] = dinv[s];
            }
            __syncthreads();
            int e = 0;
            for (; e + 3 < nb; e += 4) {
                #pragma unroll
                for (int u = 0; u < 4; ++u) {
                    const float* rp = H + (size_t)s_src[e + u] * D + t * EPT;
                    float w = s_w[e + u];
                    if (EPT == 4) {
                        float4 v = *(const float4*)rp;
                        acc[u][0] = fmaf(w, v.x, acc[u][0]);
                        acc[u][1] = fmaf(w, v.y, acc[u][1]);
                        acc[u][2] = fmaf(w, v.z, acc[u][2]);
                        acc[u][3] = fmaf(w, v.w, acc[u][3]);
                    } else {
                        float2 v = *(const float2*)rp;
                        acc[u][0] = fmaf(w, v.x, acc[u][0]);
                        acc[u][1] = fmaf(w, v.y, acc[u][1]);
                    }
                }
            }
            for (; e < nb; ++e) {
                const float* rp = H + (size_t)s_src[e] * D + t * EPT;
                float w = s_w[e];
                if (EPT == 4) {
                    float4 v = *(const float4*)rp;
                    acc[0][0] = fmaf(w, v.x, acc[0][0]);
                    acc[0][1] = fmaf(w, v.y, acc[0][1]);
                    acc[0][2] = fmaf(w, v.z, acc[0][2]);
                    acc[0][3] = fmaf(w, v.w, acc[0][3]);
                } else {
                    float2 v = *(const float2*)rp;
                    acc[0][0] = fmaf(w, v.x, acc[0][0]);
                    acc[0][1] = fmaf(w, v.y, acc[0][1]);
                }
            }
        }
        #pragma unroll
        for (int j = 0; j < EPT; ++j) {
            float v = di * ((acc[0][j] + acc[1][j]) + (acc[2][j] + acc[3][j]));
            if (bias) v += bias[t * EPT + j];
            if (doRelu) v = fmaxf(v, 0.0f);
            vout[j] = v;
        }
    }

    if (outRows) {
        if (i < N_NODES) {
            float* dst = outRows + (size_t)i * D + t * EPT;
            if (EPT == 4) {
                float4 o; o.x = vout[0]; o.y = vout[1]; o.z = vout[2]; o.w = vout[3];
                *(float4*)dst = o;
            } else {
                float2 o; o.x = vout[0]; o.y = vout[1];
                *(float2*)dst = o;
            }
        }
    } else {
        size_t base = (size_t)i * D + t * EPT;
        #pragma unroll
        for (int j = 0; j < EPT; j += 2) {
            __half h0, l0, h1, l1;
            split_f32(vout[j], h0, l0);
            split_f32(vout[j + 1], h1, l1);
            __half2 hp; hp.x = h0; hp.y = h1;
            __half2 lp; lp.x = l0; lp.y = l1;
            *(__half2*)(Oh + base + j) = hp;
            *(__half2*)(Ol + base + j) = lp;
        }
    }
}

// ---------------- WMMA fp16x2 GEMM, 3-stage cp.async pipeline ----------------
// C[128, BN] per CTA; K' = 2K via segments (Ah,Bh), (Al,Bh).
// 256 threads = 8 warps; warp computes 32 x (BN/2) via 16x16x16 frags.
template <int BN>
__global__ __launch_bounds__(256) void gemm_wmma_kernel(
    const __half* __restrict__ Ah, const __half* __restrict__ Al,
    const __half* __restrict__ Bh,
    const float* __restrict__ bias, int doRelu,
    float* __restrict__ outRows, int outN,
    __half* __restrict__ Oh, __half* __restrict__ Ol, int outK,
    int K, int N) {
    constexpr int A_LD = 40;            // 32 + 8 pad (halves)
    constexpr int B_LD = BN + 8;
    constexpr int A_BYTES = 128 * A_LD * 2;
    constexpr int B_BYTES = 32 * B_LD * 2;
    constexpr int STAGE = A_BYTES + B_BYTES;
    constexpr int WN = BN / 2;          // warp col span (64 or 32)
    constexpr int NF = WN / 16;         // n-frags per warp

    extern __shared__ char sm[];
    int tid = threadIdx.x;
    int wid = tid >> 5;
    int mt = blockIdx.x, nt = blockIdx.y;
    int row0 = mt * 128, bn0 = nt * BN;
    int KT = K >> 5;
    int total = 2 * KT;

    auto As = [&](int s) { return (__half*)(sm + s * STAGE); };
    auto Bs = [&](int s) { return (__half*)(sm + s * STAGE + A_BYTES); };

    auto issue = [&](int u) {
        int s = u % 3;
        int seg = (u < KT) ? 0 : 1;
        int k0 = (u - seg * KT) << 5;
        const __half* Asrc = seg ? Al : Ah;
        #pragma unroll
        for (int c = 0; c < 2; ++c) {
            int chunk = tid + c * 256;
            int row = chunk >> 2, col8 = (chunk & 3) * 8;
            u32 dst = smem_u32(As(s) + row * A_LD + col8);
            cp_async16(dst, Asrc + (size_t)(row0 + row) * K + k0 + col8);
        }
        constexpr int NCB = 32 * BN / 8 / 256;  // 2 (BN=128) or 1 (BN=64)
        #pragma unroll
        for (int c = 0; c < NCB; ++c) {
            int chunk = tid + c * 256;
            int r = chunk / (BN / 8), c8 = (chunk % (BN / 8)) * 8;
            u32 dst = smem_u32(Bs(s) + r * B_LD + c8);
            cp_async16(dst, Bh + (size_t)(k0 + r) * N + bn0 + c8);
        }
        cp_commit();
    };

    int wm = (wid & 3) * 32;
    int wn = (wid >> 2) * WN;

    wmma::fragment<wmma::accumulator, 16, 16, 16, float> acc[2][NF];
    #pragma unroll
    for (int mi = 0; mi < 2; ++mi)
        #pragma unroll
        for (int ni = 0; ni < NF; ++ni) wmma::fill_fragment(acc[mi][ni], 0.0f);

    int issued = 0;
    for (int p = 0; p < 2 && issued < total; ++p) issue(issued++);
    for (int u = 0; u < total; ++u) {
        if (issued < total) issue(issued++);
        cp_wait_dyn(issued - u - 1);
        __syncthreads();
        int s = u % 3;
        const __half* a = As(s);
        const __half* b = Bs(s);
        #pragma unroll
        for (int kf = 0; kf < 2; ++kf) {
            wmma::fragment<wmma::matrix_a, 16, 16, 16, __half, wmma::row_major> af[2];
            wmma::fragment<wmma::matrix_b, 16, 16, 16, __half, wmma::row_major> bf[NF];
            #pragma unroll
            for (int mi = 0; mi < 2; ++mi)
                wmma::load_matrix_sync(af[mi], a + (wm + mi * 16) * A_LD + kf * 16, A_LD);
            #pragma unroll
            for (int ni = 0; ni < NF; ++ni)
                wmma::load_matrix_sync(bf[ni], b + (kf * 16) * B_LD + wn + ni * 16, B_LD);
            #pragma unroll
            for (int mi = 0; mi < 2; ++mi)
                #pragma unroll
                for (int ni = 0; ni < NF; ++ni)
                    wmma::mma_sync(acc[mi][ni], af[mi], bf[ni], acc[mi][ni]);
        }
        __syncthreads();
    }

    // epilogue via smem
    float* Cs = (float*)sm;
    #pragma unroll
    for (int mi = 0; mi < 2; ++mi)
        #pragma unroll
        for (int ni = 0; ni < NF; ++ni)
            wmma::store_matrix_sync(Cs + (wm + mi * 16) * BN + wn + ni * 16,
                                    acc[mi][ni], BN, wmma::mem_row_major);
    __syncthreads();

    for (int idx = tid; idx < 128 * BN; idx += 256) {
        int r = idx / BN, c = idx % BN;
        float v = Cs[idx];
        if (bias) v += bias[bn0 + c];
        if (doRelu) v = fmaxf(v, 0.0f);
        int m = row0 + r;
        if (outRows) {
            if (m < N_NODES) outRows[(size_t)m * outN + bn0 + c] = v;
        } else {
            __half h, l;
            split_f32(v, h, l);
            size_t base = (size_t)m * outK + bn0 + c;
            Oh[base] = h;
            Ol[base] = l;
        }
    }
}

// ---------------- last-layer small GEMM: [N,64] @ [64,2] ----------------
__global__ void gemm64x2_kernel(const float* __restrict__ H, const float* __restrict__ W,
                                float* __restrict__ T, int n) {
    __shared__ float w[128];
    if (threadIdx.x < 128) w[threadIdx.x] = W[threadIdx.x];
    __syncthreads();
    int i = blockIdx.x * blockDim.x + threadIdx.x;
    if (i >= n) return;
    const float* h = H + (size_t)i * 64;
    float a0 = 0.f, a1 = 0.f;
    #pragma unroll
    for (int k = 0; k < 64; ++k) {
        float x = h[k];
        a0 = fmaf(x, w[2 * k], a0);
        a1 = fmaf(x, w[2 * k + 1], a1);
    }
    T[2 * i] = a0;
    T[2 * i + 1] = a1;
}

// ---------------- final aggregation (dim 2) + bias + log_softmax ----------------
__global__ void agg2_lsm_kernel(const float* __restrict__ T, const float* __restrict__ b,
                                float* __restrict__ out,
                                const int* __restrict__ off, const int* __restrict__ srcs,
                                const float* __restrict__ dinv, int n) {
    int i = blockIdx.x * blockDim.x + threadIdx.x;
    if (i >= n) return;
    float di = dinv[i];
    float a0 = di * T[2 * i];
    float a1 = di * T[2 * i + 1];
    int s0 = off[i], s1 = off[i + 1];
    for (int e = s0; e < s1; ++e) {
        int s = srcs[e];
        float w = dinv[s];
        a0 = fmaf(w, T[2 * s], a0);
        a1 = fmaf(w, T[2 * s + 1], a1);
    }
    float z0 = fmaf(di, a0, b[0]);
    float z1 = fmaf(di, a1, b[1]);
    float m = fmaxf(z0, z1);
    float lse = m + logf(expf(z0 - m) + expf(z1 - m));
    out[2 * i] = z0 - lse;
    out[2 * i + 1] = z1 - lse;
}

// ---------------- host launch ----------------
extern "C" void kernel_launch(void* const* d_in, const int* in_sizes, int n_in,
                              void* d_out, int out_size) {
    const float* x  = (const float*)d_in[0];
    const void*  ei = d_in[1];
    const float* W1 = (const float*)d_in[2];  const float* b1 = (const float*)d_in[3];
    const float* W2 = (const float*)d_in[4];  const float* b2 = (const float*)d_in[5];
    const float* W3 = (const float*)d_in[6];  const float* b3 = (const float*)d_in[7];
    const float* W4 = (const float*)d_in[8];  const float* b4 = (const float*)d_in[9];
    const float* W5 = (const float*)d_in[10]; const float* b5 = (const float*)d_in[11];
    float* out = (float*)d_out;

    const int N = N_NODES;
    const int E = N_EDGES;

    int *cnt, *off, *cur, *srcs, *bsum;
    float *dinv, *buf0, *buf1;
    __half *ah0, *al0, *ah1, *al1, *bb1, *bb2, *bb3, *bb4;
    cudaGetSymbolAddress((void**)&cnt,  g_cnt);
    cudaGetSymbolAddress((void**)&off,  g_off);
    cudaGetSymbolAddress((void**)&cur,  g_cur);
    cudaGetSymbolAddress((void**)&srcs, g_srcs);
    cudaGetSymbolAddress((void**)&bsum, g_bsum);
    cudaGetSymbolAddress((void**)&dinv, g_dinv);
    cudaGetSymbolAddress((void**)&buf0, g_buf0);
    cudaGetSymbolAddress((void**)&buf1, g_buf1);
    cudaGetSymbolAddress((void**)&ah0,  g_ah0);
    cudaGetSymbolAddress((void**)&al0,  g_al0);
    cudaGetSymbolAddress((void**)&ah1,  g_ah1);
    cudaGetSymbolAddress((void**)&al1,  g_al1);
    cudaGetSymbolAddress((void**)&bb1,  g_b1);
    cudaGetSymbolAddress((void**)&bb2,  g_b2);
    cudaGetSymbolAddress((void**)&bb3,  g_b3);
    cudaGetSymbolAddress((void**)&bb4,  g_b4);

    // smem: 3 pipeline stages vs fp32 epilogue tile, take max
    const int STAGE128 = 128 * 40 * 2 + 32 * 136 * 2;  // 18944
    const int STAGE64  = 128 * 40 * 2 + 32 * 72 * 2;   // 14848
    const int SMEM128 = (3 * STAGE128 > 128 * 128 * 4) ? 3 * STAGE128 : 128 * 128 * 4;  // 65536
    const int SMEM64  = (3 * STAGE64 > 128 * 64 * 4) ? 3 * STAGE64 : 128 * 64 * 4;      // 44544
    cudaFuncSetAttribute(gemm_wmma_kernel<128>, cudaFuncAttributeMaxDynamicSharedMemorySize, SMEM128);
    cudaFuncSetAttribute(gemm_wmma_kernel<64>,  cudaFuncAttributeMaxDynamicSharedMemorySize, SMEM64);

    // ---- graph preprocessing + weight conversion ----
    detect_kernel<<<1, 32>>>(ei);
    zero_cnt_kernel<<<(N + 255) / 256, 256>>>(cnt, N);
    count_kernel<<<(E + 255) / 256, 256>>>(ei, cnt, E);
    decomp_all_kernel<<<(W1_SZ + W2_SZ + W3_SZ + W4_SZ + 255) / 256, 256>>>(
        W1, W2, W3, W4, bb1, bb2, bb3, bb4);
    scan1_kernel<<<SCAN_NB, SCAN_BLK>>>(cnt, off, bsum, N);
    scan2_kernel<<<1, SCAN_BLK>>>(bsum, off, SCAN_NB, N);
    scan3_kernel<<<(N + 255) / 256, 256>>>(cnt, off, cur, dinv, bsum, N);
    fill_kernel<<<(E + 255) / 256, 256>>>(ei, cur, srcs, E);
    sortseg_kernel<<<(N + 255) / 256, 256>>>(off, srcs, N);

    // L1: agg(x, D=128) -> hi/lo set0 ; gemm K=128 N=256 +b1+relu -> rows buf0
    agg_kernel<4><<<PAD_ROWS, 32>>>(x, off, srcs, dinv, nullptr, 0, 128, nullptr, ah0, al0);
    gemm_wmma_kernel<128><<<dim3(MT_COUNT, 2), 256, SMEM128>>>(
        ah0, al0, bb1, b1, 1, buf0, 256, nullptr, nullptr, 0, 128, 256);

    // L2: agg(buf0, D=256) -> hi/lo set0 ; gemm K=256 N=512 +b2+relu -> hi/lo set1
    agg_kernel<4><<<PAD_ROWS, 64>>>(buf0, off, srcs, dinv, nullptr, 0, 256, nullptr, ah0, al0);
    gemm_wmma_kernel<128><<<dim3(MT_COUNT, 4), 256, SMEM128>>>(
        ah0, al0, bb2, b2, 1, nullptr, 0, ah1, al1, 512, 256, 512);

    // L3: gemm K=512 N=256 -> rows buf1 ; agg(+b3+relu) -> hi/lo set0
    gemm_wmma_kernel<128><<<dim3(MT_COUNT, 2), 256, SMEM128>>>(
        ah1, al1, bb3, nullptr, 0, buf1, 256, nullptr, nullptr, 0, 512, 256);
    agg_kernel<4><<<PAD_ROWS, 64>>>(buf1, off, srcs, dinv, b3, 1, 256, nullptr, ah0, al0);

    // L4: gemm K=256 N=64 -> rows buf0 ; agg(+b4+relu) -> rows buf1 (D=64)
    gemm_wmma_kernel<64><<<dim3(MT_COUNT, 1), 256, SMEM64>>>(
        ah0, al0, bb4, nullptr, 0, buf0, 64, nullptr, nullptr, 0, 256, 64);
    agg_kernel<2><<<N, 32>>>(buf0, off, srcs, dinv, b4, 1, 64, buf1, nullptr, nullptr);

    // L5: gemm [N,64]@[64,2] -> buf0 ; agg(dim2) + b5 + log_softmax -> out
    gemm64x2_kernel<<<(N + 127) / 128, 128>>>(buf1, W5, buf0, N);
    agg2_lsm_kernel<<<(N + 255) / 256, 256>>>(buf0, b5, out, off, srcs, dinv, N);
}

// round 8
// speedup vs baseline: 3.3565x; 1.4508x over previous
#include <cuda_runtime.h>
#include <cuda_fp16.h>
#include <mma.h>
#include <math.h>
#include <stdint.h>

using namespace nvcuda;

#define N_NODES 50000
#define N_EDGES 400000
#define MT_COUNT 392                 // padded row tiles: 392*128 = 50176
#define PAD_ROWS (MT_COUNT * 128)
#define SCAN_BLK 256
#define SCAN_NB ((N_NODES + SCAN_BLK - 1) / SCAN_BLK)

typedef unsigned int u32;
typedef unsigned long long u64;

// ---------------- scratch (static device globals; no allocs) ----------------
__device__ int   g_is64;
__device__ int   g_cnt[N_NODES];
__device__ int   g_off[N_NODES + 1];
__device__ int   g_cur[N_NODES];
__device__ int   g_srcs[N_EDGES];
__device__ int   g_bsum[SCAN_BLK];
__device__ float g_dinv[N_NODES];
__device__ float g_buf0[(size_t)N_NODES * 512];
__device__ float g_buf1[(size_t)N_NODES * 512];
// A-operand fp16 row-major buffers (two ping-pong sets)
__device__ __half g_ah0[(size_t)PAD_ROWS * 512];
__device__ __half g_ah1[(size_t)PAD_ROWS * 512];
// B-operand fp16 row-major [K,N], one buffer per layer
__device__ __half g_b1[128 * 256];
__device__ __half g_b2[256 * 512];
__device__ __half g_b3[512 * 256];
__device__ __half g_b4[256 * 64];

// ---------------- helpers ----------------
__device__ __forceinline__ u32 smem_u32(const void* p) {
    return (u32)__cvta_generic_to_shared(p);
}
__device__ __forceinline__ void cp_async16(u32 dst, const void* src) {
    asm volatile("cp.async.cg.shared.global [%0], [%1], 16;" :: "r"(dst), "l"(src));
}
__device__ __forceinline__ void cp_commit() {
    asm volatile("cp.async.commit_group;" ::: "memory");
}
__device__ __forceinline__ void cp_wait_dyn(int n) {
    if (n <= 0)      asm volatile("cp.async.wait_group 0;" ::: "memory");
    else if (n == 1) asm volatile("cp.async.wait_group 1;" ::: "memory");
    else             asm volatile("cp.async.wait_group 2;" ::: "memory");
}

// ---------------- edge dtype detection (warp-parallel) ----------------
__global__ void detect_kernel(const void* eiv) {
    const long long* p = (const long long*)eiv;
    int t = threadIdx.x;
    int bad = 0;
    #pragma unroll
    for (int e = t; e < 256; e += 32) {
        long long v = p[e];
        if (v < 0 || v >= N_NODES) bad = 1;
    }
    unsigned m = __ballot_sync(0xFFFFFFFFu, bad);
    if (t == 0) g_is64 = (m == 0u);
}
__device__ __forceinline__ int load_src(const void* eiv, int E, int e) {
    return g_is64 ? (int)((const long long*)eiv)[e] : ((const int*)eiv)[e];
}
__device__ __forceinline__ int load_dst(const void* eiv, int E, int e) {
    return g_is64 ? (int)((const long long*)eiv)[E + e] : ((const int*)eiv)[E + e];
}

// ---------------- preprocessing ----------------
__global__ void zero_cnt_kernel(int* cnt, int n) {
    int i = blockIdx.x * blockDim.x + threadIdx.x;
    if (i < n) cnt[i] = 0;
}
__global__ void count_kernel(const void* __restrict__ eiv, int* cnt, int E) {
    int e = blockIdx.x * blockDim.x + threadIdx.x;
    if (e < E) atomicAdd(&cnt[load_dst(eiv, E, e)], 1);
}
__global__ void scan1_kernel(const int* __restrict__ cnt, int* __restrict__ off,
                             int* __restrict__ bsum, int n) {
    __shared__ int sh[SCAN_BLK];
    int t = threadIdx.x;
    int i = blockIdx.x * SCAN_BLK + t;
    int v = (i < n) ? cnt[i] : 0;
    sh[t] = v;
    __syncthreads();
    for (int d = 1; d < SCAN_BLK; d <<= 1) {
        int x = 0;
        if (t >= d) x = sh[t - d];
        __syncthreads();
        if (t >= d) sh[t] += x;
        __syncthreads();
    }
    if (i < n) off[i] = sh[t] - v;
    if (t == SCAN_BLK - 1) bsum[blockIdx.x] = sh[t];
}
__global__ void scan2_kernel(int* __restrict__ bsum, int* __restrict__ off, int nb, int n) {
    __shared__ int sh[SCAN_BLK];
    int t = threadIdx.x;
    int v = (t < nb) ? bsum[t] : 0;
    sh[t] = v;
    __syncthreads();
    for (int d = 1; d < SCAN_BLK; d <<= 1) {
        int x = 0;
        if (t >= d) x = sh[t - d];
        __syncthreads();
        if (t >= d) sh[t] += x;
        __syncthreads();
    }
    if (t < nb) bsum[t] = sh[t] - v;
    if (t == nb - 1) off[n] = sh[t];
}
__global__ void scan3_kernel(const int* __restrict__ cnt, int* __restrict__ off,
                             int* __restrict__ cur, float* __restrict__ dinv,
                             const int* __restrict__ bsum, int n) {
    int i = blockIdx.x * blockDim.x + threadIdx.x;
    if (i < n) {
        int o = off[i] + bsum[i >> 8];
        off[i] = o;
        cur[i] = o;
        dinv[i] = rsqrtf((float)(cnt[i] + 1));
    }
}
__global__ void fill_kernel(const void* __restrict__ eiv, int* cur,
                            int* __restrict__ srcs, int E) {
    int e = blockIdx.x * blockDim.x + threadIdx.x;
    if (e < E) {
        int d = load_dst(eiv, E, e);
        int pos = atomicAdd(&cur[d], 1);
        srcs[pos] = load_src(eiv, E, e);
    }
}
__global__ void sortseg_kernel(const int* __restrict__ off, int* __restrict__ srcs, int n) {
    int i = blockIdx.x * blockDim.x + threadIdx.x;
    if (i >= n) return;
    int s0 = off[i], s1 = off[i + 1];
    for (int a = s0 + 1; a < s1; ++a) {
        int key = srcs[a];
        int b = a - 1;
        while (b >= s0 && srcs[b] > key) { srcs[b + 1] = srcs[b]; --b; }
        srcs[b + 1] = key;
    }
}

// ---------------- fused weight conversion W1..W4 -> fp16 ----------------
#define W1_SZ (128 * 256)
#define W2_SZ (256 * 512)
#define W3_SZ (512 * 256)
#define W4_SZ (256 * 64)
__global__ void decomp_all_kernel(const float* __restrict__ W1, const float* __restrict__ W2,
                                  const float* __restrict__ W3, const float* __restrict__ W4,
                                  __half* __restrict__ B1, __half* __restrict__ B2,
                                  __half* __restrict__ B3, __half* __restrict__ B4) {
    int e = blockIdx.x * blockDim.x + threadIdx.x;
    int total = W1_SZ + W2_SZ + W3_SZ + W4_SZ;
    if (e >= total) return;
    if (e < W1_SZ) { B1[e] = __float2half(W1[e]); return; }
    e -= W1_SZ;
    if (e < W2_SZ) { B2[e] = __float2half(W2[e]); return; }
    e -= W2_SZ;
    if (e < W3_SZ) { B3[e] = __float2half(W3[e]); return; }
    e -= W3_SZ;
    B4[e] = __float2half(W4[e]);
}

// ---------------- aggregation v3: warp per node, no smem, no barriers ----------------
// out[i] = dinv[i]*(dinv[i]*h[i] + sum dinv[s]*h[s]) (+bias, relu)
// 8 warps per block = 8 nodes per block. Lane handles F = D/32 contiguous floats.
// Output fp32 rows OR fp16 rows (zeros on padding rows).
template <int D>
__global__ __launch_bounds__(256) void agg_warp_kernel(
    const float* __restrict__ H,
    const int* __restrict__ off, const int* __restrict__ srcs,
    const float* __restrict__ dinv,
    const float* __restrict__ bias, int doRelu, int nTotal,
    float* __restrict__ outRows, __half* __restrict__ Oh) {
    constexpr int F = D / 32;
    int lane = threadIdx.x & 31;
    int i = blockIdx.x * 8 + (threadIdx.x >> 5);
    if (i >= nTotal) return;

    float vout[F];
    #pragma unroll
    for (int j = 0; j < F; ++j) vout[j] = 0.0f;

    if (i < N_NODES) {
        float di = dinv[i];
        float acc[F], acc2[F];
        const float* own = H + (size_t)i * D + lane * F;
        #pragma unroll
        for (int j4 = 0; j4 < F; j4 += 4) {
            float4 v = *(const float4*)(own + j4);
            acc[j4 + 0] = di * v.x; acc[j4 + 1] = di * v.y;
            acc[j4 + 2] = di * v.z; acc[j4 + 3] = di * v.w;
        }
        #pragma unroll
        for (int j = 0; j < F; ++j) acc2[j] = 0.0f;

        int s0 = off[i], s1 = off[i + 1];
        for (int base = s0; base < s1; base += 32) {
            int nb = s1 - base; if (nb > 32) nb = 32;
            int sid = 0; float wv = 0.0f;
            if (lane < nb) { sid = srcs[base + lane]; wv = dinv[sid]; }
            int e = 0;
            for (; e + 1 < nb; e += 2) {
                int sa = __shfl_sync(0xFFFFFFFFu, sid, e);
                float wa = __shfl_sync(0xFFFFFFFFu, wv, e);
                int sb = __shfl_sync(0xFFFFFFFFu, sid, e + 1);
                float wb = __shfl_sync(0xFFFFFFFFu, wv, e + 1);
                const float* ra = H + (size_t)sa * D + lane * F;
                const float* rb = H + (size_t)sb * D + lane * F;
                #pragma unroll
                for (int j4 = 0; j4 < F; j4 += 4) {
                    float4 va = *(const float4*)(ra + j4);
                    float4 vb = *(const float4*)(rb + j4);
                    acc[j4 + 0]  = fmaf(wa, va.x, acc[j4 + 0]);
                    acc[j4 + 1]  = fmaf(wa, va.y, acc[j4 + 1]);
                    acc[j4 + 2]  = fmaf(wa, va.z, acc[j4 + 2]);
                    acc[j4 + 3]  = fmaf(wa, va.w, acc[j4 + 3]);
                    acc2[j4 + 0] = fmaf(wb, vb.x, acc2[j4 + 0]);
                    acc2[j4 + 1] = fmaf(wb, vb.y, acc2[j4 + 1]);
                    acc2[j4 + 2] = fmaf(wb, vb.z, acc2[j4 + 2]);
                    acc2[j4 + 3] = fmaf(wb, vb.w, acc2[j4 + 3]);
                }
            }
            if (e < nb) {
                int sa = __shfl_sync(0xFFFFFFFFu, sid, e);
                float wa = __shfl_sync(0xFFFFFFFFu, wv, e);
                const float* ra = H + (size_t)sa * D + lane * F;
                #pragma unroll
                for (int j4 = 0; j4 < F; j4 += 4) {
                    float4 va = *(const float4*)(ra + j4);
                    acc[j4 + 0] = fmaf(wa, va.x, acc[j4 + 0]);
                    acc[j4 + 1] = fmaf(wa, va.y, acc[j4 + 1]);
                    acc[j4 + 2] = fmaf(wa, va.z, acc[j4 + 2]);
                    acc[j4 + 3] = fmaf(wa, va.w, acc[j4 + 3]);
                }
            }
        }
        #pragma unroll
        for (int j = 0; j < F; ++j) {
            float v = di * (acc[j] + acc2[j]);
            if (bias) v += bias[lane * F + j];
            if (doRelu) v = fmaxf(v, 0.0f);
            vout[j] = v;
        }
    }

    if (outRows) {
        if (i < N_NODES) {
            float* dst = outRows + (size_t)i * D + lane * F;
            #pragma unroll
            for (int j4 = 0; j4 < F; j4 += 4) {
                float4 o; o.x = vout[j4]; o.y = vout[j4 + 1]; o.z = vout[j4 + 2]; o.w = vout[j4 + 3];
                *(float4*)(dst + j4) = o;
            }
        }
    } else {
        __half* dst = Oh + (size_t)i * D + lane * F;
        #pragma unroll
        for (int j4 = 0; j4 < F; j4 += 4) {
            __half2 p0; p0.x = __float2half(vout[j4 + 0]); p0.y = __float2half(vout[j4 + 1]);
            __half2 p1; p1.x = __float2half(vout[j4 + 2]); p1.y = __float2half(vout[j4 + 3]);
            *(__half2*)(dst + j4) = p0;
            *(__half2*)(dst + j4 + 2) = p1;
        }
    }
}

// D=64 variant (F=2): float2 path
__global__ __launch_bounds__(256) void agg_warp64_kernel(
    const float* __restrict__ H,
    const int* __restrict__ off, const int* __restrict__ srcs,
    const float* __restrict__ dinv,
    const float* __restrict__ bias, int doRelu, int nTotal,
    float* __restrict__ outRows) {
    int lane = threadIdx.x & 31;
    int i = blockIdx.x * 8 + (threadIdx.x >> 5);
    if (i >= nTotal || i >= N_NODES) return;
    float di = dinv[i];
    const float2* own = (const float2*)(H + (size_t)i * 64) + lane;
    float2 h = *own;
    float a0 = di * h.x, a1 = di * h.y, b0 = 0.f, b1 = 0.f;
    int s0 = off[i], s1 = off[i + 1];
    for (int base = s0; base < s1; base += 32) {
        int nb = s1 - base; if (nb > 32) nb = 32;
        int sid = 0; float wv = 0.0f;
        if (lane < nb) { sid = srcs[base + lane]; wv = dinv[sid]; }
        int e = 0;
        for (; e + 1 < nb; e += 2) {
            int sa = __shfl_sync(0xFFFFFFFFu, sid, e);
            float wa = __shfl_sync(0xFFFFFFFFu, wv, e);
            int sb = __shfl_sync(0xFFFFFFFFu, sid, e + 1);
            float wb = __shfl_sync(0xFFFFFFFFu, wv, e + 1);
            float2 va = *((const float2*)(H + (size_t)sa * 64) + lane);
            float2 vb = *((const float2*)(H + (size_t)sb * 64) + lane);
            a0 = fmaf(wa, va.x, a0); a1 = fmaf(wa, va.y, a1);
            b0 = fmaf(wb, vb.x, b0); b1 = fmaf(wb, vb.y, b1);
        }
        if (e < nb) {
            int sa = __shfl_sync(0xFFFFFFFFu, sid, e);
            float wa = __shfl_sync(0xFFFFFFFFu, wv, e);
            float2 va = *((const float2*)(H + (size_t)sa * 64) + lane);
            a0 = fmaf(wa, va.x, a0); a1 = fmaf(wa, va.y, a1);
        }
    }
    float v0 = di * (a0 + b0) + bias[lane * 2];
    float v1 = di * (a1 + b1) + bias[lane * 2 + 1];
    if (doRelu) { v0 = fmaxf(v0, 0.f); v1 = fmaxf(v1, 0.f); }
    float2 o; o.x = v0; o.y = v1;
    *((float2*)(outRows + (size_t)i * 64) + lane) = o;
}

// ---------------- WMMA fp16 GEMM, 3-stage cp.async pipeline ----------------
// C[128, BN] per CTA; 256 threads = 8 warps; warp computes 32 x (BN/2).
template <int BN>
__global__ __launch_bounds__(256) void gemm_wmma_kernel(
    const __half* __restrict__ Ah, const __half* __restrict__ Bh,
    const float* __restrict__ bias, int doRelu,
    float* __restrict__ outRows, int outN,
    __half* __restrict__ Oh, int outK,
    int K, int N) {
    constexpr int A_LD = 40;            // 32 + 8 pad (halves)
    constexpr int B_LD = BN + 8;
    constexpr int A_BYTES = 128 * A_LD * 2;
    constexpr int B_BYTES = 32 * B_LD * 2;
    constexpr int STAGE = A_BYTES + B_BYTES;
    constexpr int WN = BN / 2;          // warp col span (64 or 32)
    constexpr int NF = WN / 16;         // n-frags per warp

    extern __shared__ char sm[];
    int tid = threadIdx.x;
    int wid = tid >> 5;
    int mt = blockIdx.x, nt = blockIdx.y;
    int row0 = mt * 128, bn0 = nt * BN;
    int total = K >> 5;

    auto As = [&](int s) { return (__half*)(sm + s * STAGE); };
    auto Bs = [&](int s) { return (__half*)(sm + s * STAGE + A_BYTES); };

    auto issue = [&](int u) {
        int s = u % 3;
        int k0 = u << 5;
        #pragma unroll
        for (int c = 0; c < 2; ++c) {
            int chunk = tid + c * 256;
            int row = chunk >> 2, col8 = (chunk & 3) * 8;
            u32 dst = smem_u32(As(s) + row * A_LD + col8);
            cp_async16(dst, Ah + (size_t)(row0 + row) * K + k0 + col8);
        }
        constexpr int NCB = 32 * BN / 8 / 256;  // 2 (BN=128) or 1 (BN=64)
        #pragma unroll
        for (int c = 0; c < NCB; ++c) {
            int chunk = tid + c * 256;
            int r = chunk / (BN / 8), c8 = (chunk % (BN / 8)) * 8;
            u32 dst = smem_u32(Bs(s) + r * B_LD + c8);
            cp_async16(dst, Bh + (size_t)(k0 + r) * N + bn0 + c8);
        }
        cp_commit();
    };

    int wm = (wid & 3) * 32;
    int wn = (wid >> 2) * WN;

    wmma::fragment<wmma::accumulator, 16, 16, 16, float> acc[2][NF];
    #pragma unroll
    for (int mi = 0; mi < 2; ++mi)
        #pragma unroll
        for (int ni = 0; ni < NF; ++ni) wmma::fill_fragment(acc[mi][ni], 0.0f);

    int issued = 0;
    for (int p = 0; p < 2 && issued < total; ++p) issue(issued++);
    for (int u = 0; u < total; ++u) {
        if (issued < total) issue(issued++);
        cp_wait_dyn(issued - u - 1);
        __syncthreads();
        int s = u % 3;
        const __half* a = As(s);
        const __half* b = Bs(s);
        #pragma unroll
        for (int kf = 0; kf < 2; ++kf) {
            wmma::fragment<wmma::matrix_a, 16, 16, 16, __half, wmma::row_major> af[2];
            wmma::fragment<wmma::matrix_b, 16, 16, 16, __half, wmma::row_major> bf[NF];
            #pragma unroll
            for (int mi = 0; mi < 2; ++mi)
                wmma::load_matrix_sync(af[mi], a + (wm + mi * 16) * A_LD + kf * 16, A_LD);
            #pragma unroll
            for (int ni = 0; ni < NF; ++ni)
                wmma::load_matrix_sync(bf[ni], b + (kf * 16) * B_LD + wn + ni * 16, B_LD);
            #pragma unroll
            for (int mi = 0; mi < 2; ++mi)
                #pragma unroll
                for (int ni = 0; ni < NF; ++ni)
                    wmma::mma_sync(acc[mi][ni], af[mi], bf[ni], acc[mi][ni]);
        }
        __syncthreads();
    }

    // epilogue via smem
    float* Cs = (float*)sm;
    #pragma unroll
    for (int mi = 0; mi < 2; ++mi)
        #pragma unroll
        for (int ni = 0; ni < NF; ++ni)
            wmma::store_matrix_sync(Cs + (wm + mi * 16) * BN + wn + ni * 16,
                                    acc[mi][ni], BN, wmma::mem_row_major);
    __syncthreads();

    for (int idx = tid; idx < 128 * BN; idx += 256) {
        int r = idx / BN, c = idx % BN;
        float v = Cs[idx];
        if (bias) v += bias[bn0 + c];
        if (doRelu) v = fmaxf(v, 0.0f);
        int m = row0 + r;
        if (outRows) {
            if (m < N_NODES) outRows[(size_t)m * outN + bn0 + c] = v;
        } else {
            Oh[(size_t)m * outK + bn0 + c] = __float2half(v);
        }
    }
}

// ---------------- last-layer small GEMM: [N,64] @ [64,2] ----------------
__global__ void gemm64x2_kernel(const float* __restrict__ H, const float* __restrict__ W,
                                float* __restrict__ T, int n) {
    __shared__ float w[128];
    if (threadIdx.x < 128) w[threadIdx.x] = W[threadIdx.x];
    __syncthreads();
    int i = blockIdx.x * blockDim.x + threadIdx.x;
    if (i >= n) return;
    const float* h = H + (size_t)i * 64;
    float a0 = 0.f, a1 = 0.f;
    #pragma unroll
    for (int k = 0; k < 64; ++k) {
        float x = h[k];
        a0 = fmaf(x, w[2 * k], a0);
        a1 = fmaf(x, w[2 * k + 1], a1);
    }
    T[2 * i] = a0;
    T[2 * i + 1] = a1;
}

// ---------------- final aggregation (dim 2) + bias + log_softmax ----------------
__global__ void agg2_lsm_kernel(const float* __restrict__ T, const float* __restrict__ b,
                                float* __restrict__ out,
                                const int* __restrict__ off, const int* __restrict__ srcs,
                                const float* __restrict__ dinv, int n) {
    int i = blockIdx.x * blockDim.x + threadIdx.x;
    if (i >= n) return;
    float di = dinv[i];
    float a0 = di * T[2 * i];
    float a1 = di * T[2 * i + 1];
    int s0 = off[i], s1 = off[i + 1];
    for (int e = s0; e < s1; ++e) {
        int s = srcs[e];
        float w = dinv[s];
        a0 = fmaf(w, T[2 * s], a0);
        a1 = fmaf(w, T[2 * s + 1], a1);
    }
    float z0 = fmaf(di, a0, b[0]);
    float z1 = fmaf(di, a1, b[1]);
    float m = fmaxf(z0, z1);
    float lse = m + logf(expf(z0 - m) + expf(z1 - m));
    out[2 * i] = z0 - lse;
    out[2 * i + 1] = z1 - lse;
}

// ---------------- host launch ----------------
extern "C" void kernel_launch(void* const* d_in, const int* in_sizes, int n_in,
                              void* d_out, int out_size) {
    const float* x  = (const float*)d_in[0];
    const void*  ei = d_in[1];
    const float* W1 = (const float*)d_in[2];  const float* b1 = (const float*)d_in[3];
    const float* W2 = (const float*)d_in[4];  const float* b2 = (const float*)d_in[5];
    const float* W3 = (const float*)d_in[6];  const float* b3 = (const float*)d_in[7];
    const float* W4 = (const float*)d_in[8];  const float* b4 = (const float*)d_in[9];
    const float* W5 = (const float*)d_in[10]; const float* b5 = (const float*)d_in[11];
    float* out = (float*)d_out;

    const int N = N_NODES;
    const int E = N_EDGES;

    int *cnt, *off, *cur, *srcs, *bsum;
    float *dinv, *buf0, *buf1;
    __half *ah0, *ah1, *bb1, *bb2, *bb3, *bb4;
    cudaGetSymbolAddress((void**)&cnt,  g_cnt);
    cudaGetSymbolAddress((void**)&off,  g_off);
    cudaGetSymbolAddress((void**)&cur,  g_cur);
    cudaGetSymbolAddress((void**)&srcs, g_srcs);
    cudaGetSymbolAddress((void**)&bsum, g_bsum);
    cudaGetSymbolAddress((void**)&dinv, g_dinv);
    cudaGetSymbolAddress((void**)&buf0, g_buf0);
    cudaGetSymbolAddress((void**)&buf1, g_buf1);
    cudaGetSymbolAddress((void**)&ah0,  g_ah0);
    cudaGetSymbolAddress((void**)&ah1,  g_ah1);
    cudaGetSymbolAddress((void**)&bb1,  g_b1);
    cudaGetSymbolAddress((void**)&bb2,  g_b2);
    cudaGetSymbolAddress((void**)&bb3,  g_b3);
    cudaGetSymbolAddress((void**)&bb4,  g_b4);

    // smem: 3 pipeline stages vs fp32 epilogue tile, take max
    const int STAGE128 = 128 * 40 * 2 + 32 * 136 * 2;  // 18944
    const int STAGE64  = 128 * 40 * 2 + 32 * 72 * 2;   // 14848
    const int SMEM128 = (3 * STAGE128 > 128 * 128 * 4) ? 3 * STAGE128 : 128 * 128 * 4;  // 65536
    const int SMEM64  = (3 * STAGE64 > 128 * 64 * 4) ? 3 * STAGE64 : 128 * 64 * 4;      // 44544
    cudaFuncSetAttribute(gemm_wmma_kernel<128>, cudaFuncAttributeMaxDynamicSharedMemorySize, SMEM128);
    cudaFuncSetAttribute(gemm_wmma_kernel<64>,  cudaFuncAttributeMaxDynamicSharedMemorySize, SMEM64);

    // ---- graph preprocessing + weight conversion ----
    detect_kernel<<<1, 32>>>(ei);
    zero_cnt_kernel<<<(N + 255) / 256, 256>>>(cnt, N);
    count_kernel<<<(E + 255) / 256, 256>>>(ei, cnt, E);
    decomp_all_kernel<<<(W1_SZ + W2_SZ + W3_SZ + W4_SZ + 255) / 256, 256>>>(
        W1, W2, W3, W4, bb1, bb2, bb3, bb4);
    scan1_kernel<<<SCAN_NB, SCAN_BLK>>>(cnt, off, bsum, N);
    scan2_kernel<<<1, SCAN_BLK>>>(bsum, off, SCAN_NB, N);
    scan3_kernel<<<(N + 255) / 256, 256>>>(cnt, off, cur, dinv, bsum, N);
    fill_kernel<<<(E + 255) / 256, 256>>>(ei, cur, srcs, E);
    sortseg_kernel<<<(N + 255) / 256, 256>>>(off, srcs, N);

    const int AGG_BLKS = (PAD_ROWS + 7) / 8;  // 6272

    // L1: agg(x, D=128) -> fp16 ah0 ; gemm K=128 N=256 +b1+relu -> rows buf0
    agg_warp_kernel<128><<<AGG_BLKS, 256>>>(x, off, srcs, dinv, nullptr, 0, PAD_ROWS, nullptr, ah0);
    gemm_wmma_kernel<128><<<dim3(MT_COUNT, 2), 256, SMEM128>>>(
        ah0, bb1, b1, 1, buf0, 256, nullptr, 0, 128, 256);

    // L2: agg(buf0, D=256) -> fp16 ah0 ; gemm K=256 N=512 +b2+relu -> fp16 ah1
    agg_warp_kernel<256><<<AGG_BLKS, 256>>>(buf0, off, srcs, dinv, nullptr, 0, PAD_ROWS, nullptr, ah0);
    gemm_wmma_kernel<128><<<dim3(MT_COUNT, 4), 256, SMEM128>>>(
        ah0, bb2, b2, 1, nullptr, 0, ah1, 512, 256, 512);

    // L3: gemm K=512 N=256 -> rows buf1 ; agg(+b3+relu) -> fp16 ah0
    gemm_wmma_kernel<128><<<dim3(MT_COUNT, 2), 256, SMEM128>>>(
        ah1, bb3, nullptr, 0, buf1, 256, nullptr, 0, 512, 256);
    agg_warp_kernel<256><<<AGG_BLKS, 256>>>(buf1, off, srcs, dinv, b3, 1, PAD_ROWS, nullptr, ah0);

    // L4: gemm K=256 N=64 -> rows buf0 ; agg(+b4+relu) -> rows buf1 (D=64)
    gemm_wmma_kernel<64><<<dim3(MT_COUNT, 1), 256, SMEM64>>>(
        ah0, bb4, nullptr, 0, buf0, 64, nullptr, 0, 256, 64);
    agg_warp64_kernel<<<(N + 7) / 8, 256>>>(buf0, off, srcs, dinv, b4, 1, N, buf1);

    // L5: gemm [N,64]@[64,2] -> buf0 ; agg(dim2) + b5 + log_softmax -> out
    gemm64x2_kernel<<<(N + 127) / 128, 128>>>(buf1, W5, buf0, N);
    agg2_lsm_kernel<<<(N + 255) / 256, 256>>>(buf0, b5, out, off, srcs, dinv, N);
}

// round 9
// speedup vs baseline: 3.7675x; 1.1224x over previous
#include <cuda_runtime.h>
#include <cuda_fp16.h>
#include <mma.h>
#include <math.h>
#include <stdint.h>

using namespace nvcuda;

#define N_NODES 50000
#define N_EDGES 400000
#define MT_COUNT 392                 // padded row tiles: 392*128 = 50176
#define PAD_ROWS (MT_COUNT * 128)
#define SCAN_BLK 256
#define SCAN_NB ((N_NODES + SCAN_BLK - 1) / SCAN_BLK)

typedef unsigned int u32;
typedef unsigned long long u64;

// ---------------- scratch (static device globals; no allocs) ----------------
__device__ int   g_is64;
__device__ int   g_cnt[N_NODES];
__device__ int   g_off[N_NODES + 1];
__device__ int   g_cur[N_NODES];
__device__ int   g_srcs[N_EDGES];
__device__ int   g_bsum[SCAN_BLK];
__device__ float g_dinv[N_NODES];
__device__ float g_T[2 * N_NODES];
// fp16 activation ping-pong buffers, row-major [PAD_ROWS, <=512]
__device__ __half g_h0[(size_t)PAD_ROWS * 512];
__device__ __half g_h1[(size_t)PAD_ROWS * 512];
// x converted to fp16 [N_NODES,128]
__device__ __half g_xh[(size_t)N_NODES * 128];
// weights fp16
__device__ __half g_b1[128 * 256];
__device__ __half g_b2[256 * 512];
__device__ __half g_b3[512 * 256];
__device__ __half g_b4[256 * 64];

// ---------------- helpers ----------------
__device__ __forceinline__ u32 smem_u32(const void* p) {
    return (u32)__cvta_generic_to_shared(p);
}
__device__ __forceinline__ void cp_async16(u32 dst, const void* src) {
    asm volatile("cp.async.cg.shared.global [%0], [%1], 16;" :: "r"(dst), "l"(src));
}
__device__ __forceinline__ void cp_commit() {
    asm volatile("cp.async.commit_group;" ::: "memory");
}
__device__ __forceinline__ void cp_wait_dyn(int n) {
    if (n <= 0)      asm volatile("cp.async.wait_group 0;" ::: "memory");
    else if (n == 1) asm volatile("cp.async.wait_group 1;" ::: "memory");
    else             asm volatile("cp.async.wait_group 2;" ::: "memory");
}
template <int F2>
__device__ __forceinline__ void load_h2v(const __half2* p, __half2* v) {
    if (F2 == 1)      *(u32*)v  = *(const u32*)p;
    else if (F2 == 2) *(uint2*)v = *(const uint2*)p;
    else              *(uint4*)v = *(const uint4*)p;
}
template <int F2>
__device__ __forceinline__ void store_h2v(__half2* p, const __half2* v) {
    if (F2 == 1)      *(u32*)p  = *(const u32*)v;
    else if (F2 == 2) *(uint2*)p = *(const uint2*)v;
    else              *(uint4*)p = *(const uint4*)v;
}

// ---------------- edge dtype detection (warp-parallel) ----------------
__global__ void detect_kernel(const void* eiv) {
    const long long* p = (const long long*)eiv;
    int t = threadIdx.x;
    int bad = 0;
    #pragma unroll
    for (int e = t; e < 256; e += 32) {
        long long v = p[e];
        if (v < 0 || v >= N_NODES) bad = 1;
    }
    unsigned m = __ballot_sync(0xFFFFFFFFu, bad);
    if (t == 0) g_is64 = (m == 0u);
}
__device__ __forceinline__ int load_src(const void* eiv, int E, int e) {
    return g_is64 ? (int)((const long long*)eiv)[e] : ((const int*)eiv)[e];
}
__device__ __forceinline__ int load_dst(const void* eiv, int E, int e) {
    return g_is64 ? (int)((const long long*)eiv)[E + e] : ((const int*)eiv)[E + e];
}

// ---------------- preprocessing ----------------
__global__ void zero_cnt_kernel(int* cnt, int n) {
    int i = blockIdx.x * blockDim.x + threadIdx.x;
    if (i < n) cnt[i] = 0;
}
__global__ void count_kernel(const void* __restrict__ eiv, int* cnt, int E) {
    int e = blockIdx.x * blockDim.x + threadIdx.x;
    if (e < E) atomicAdd(&cnt[load_dst(eiv, E, e)], 1);
}
__global__ void scan1_kernel(const int* __restrict__ cnt, int* __restrict__ off,
                             int* __restrict__ bsum, int n) {
    __shared__ int sh[SCAN_BLK];
    int t = threadIdx.x;
    int i = blockIdx.x * SCAN_BLK + t;
    int v = (i < n) ? cnt[i] : 0;
    sh[t] = v;
    __syncthreads();
    for (int d = 1; d < SCAN_BLK; d <<= 1) {
        int x = 0;
        if (t >= d) x = sh[t - d];
        __syncthreads();
        if (t >= d) sh[t] += x;
        __syncthreads();
    }
    if (i < n) off[i] = sh[t] - v;
    if (t == SCAN_BLK - 1) bsum[blockIdx.x] = sh[t];
}
__global__ void scan2_kernel(int* __restrict__ bsum, int* __restrict__ off, int nb, int n) {
    __shared__ int sh[SCAN_BLK];
    int t = threadIdx.x;
    int v = (t < nb) ? bsum[t] : 0;
    sh[t] = v;
    __syncthreads();
    for (int d = 1; d < SCAN_BLK; d <<= 1) {
        int x = 0;
        if (t >= d) x = sh[t - d];
        __syncthreads();
        if (t >= d) sh[t] += x;
        __syncthreads();
    }
    if (t < nb) bsum[t] = sh[t] - v;
    if (t == nb - 1) off[n] = sh[t];
}
__global__ void scan3_kernel(const int* __restrict__ cnt, int* __restrict__ off,
                             int* __restrict__ cur, float* __restrict__ dinv,
                             const int* __restrict__ bsum, int n) {
    int i = blockIdx.x * blockDim.x + threadIdx.x;
    if (i < n) {
        int o = off[i] + bsum[i >> 8];
        off[i] = o;
        cur[i] = o;
        dinv[i] = rsqrtf((float)(cnt[i] + 1));
    }
}
__global__ void fill_kernel(const void* __restrict__ eiv, int* cur,
                            int* __restrict__ srcs, int E) {
    int e = blockIdx.x * blockDim.x + threadIdx.x;
    if (e < E) {
        int d = load_dst(eiv, E, e);
        int pos = atomicAdd(&cur[d], 1);
        srcs[pos] = load_src(eiv, E, e);
    }
}
__global__ void sortseg_kernel(const int* __restrict__ off, int* __restrict__ srcs, int n) {
    int i = blockIdx.x * blockDim.x + threadIdx.x;
    if (i >= n) return;
    int s0 = off[i], s1 = off[i + 1];
    for (int a = s0 + 1; a < s1; ++a) {
        int key = srcs[a];
        int b = a - 1;
        while (b >= s0 && srcs[b] > key) { srcs[b + 1] = srcs[b]; --b; }
        srcs[b + 1] = key;
    }
}

// ---------------- fused conversion: W1..W4 and x -> fp16 ----------------
#define W1_SZ (128 * 256)
#define W2_SZ (256 * 512)
#define W3_SZ (512 * 256)
#define W4_SZ (256 * 64)
#define X_SZ  (N_NODES * 128)
__global__ void decomp_all_kernel(const float* __restrict__ W1, const float* __restrict__ W2,
                                  const float* __restrict__ W3, const float* __restrict__ W4,
                                  const float* __restrict__ X,
                                  __half* __restrict__ B1, __half* __restrict__ B2,
                                  __half* __restrict__ B3, __half* __restrict__ B4,
                                  __half* __restrict__ XH) {
    int e = blockIdx.x * blockDim.x + threadIdx.x;
    if (e < W1_SZ) { B1[e] = __float2half(W1[e]); return; }
    e -= W1_SZ;
    if (e < W2_SZ) { B2[e] = __float2half(W2[e]); return; }
    e -= W2_SZ;
    if (e < W3_SZ) { B3[e] = __float2half(W3[e]); return; }
    e -= W3_SZ;
    if (e < W4_SZ) { B4[e] = __float2half(W4[e]); return; }
    e -= W4_SZ;
    if (e < X_SZ) XH[e] = __float2half(X[e]);
}

// ---------------- aggregation (fp16 in, fp16 out, fp32 accumulate) ----------------
// out[i] = dinv[i]*(dinv[i]*h[i] + sum dinv[s]*h[s]) (+bias, relu)
// Warp per node, 8 warps/block, no smem/barriers. Lane handles F2 half2's.
template <int D>
__global__ __launch_bounds__(256) void agg_h_kernel(
    const __half* __restrict__ H,
    const int* __restrict__ off, const int* __restrict__ srcs,
    const float* __restrict__ dinv,
    const float* __restrict__ bias, int doRelu, int nTotal,
    __half* __restrict__ Oh) {
    constexpr int F2 = D / 64;          // half2 per lane
    int lane = threadIdx.x & 31;
    int i = blockIdx.x * 8 + (threadIdx.x >> 5);
    if (i >= nTotal) return;

    float2 vo[F2];
    #pragma unroll
    for (int j = 0; j < F2; ++j) { vo[j].x = 0.0f; vo[j].y = 0.0f; }

    if (i < N_NODES) {
        float di = dinv[i];
        float2 acc[F2], acc2[F2];
        {
            __half2 h[F2];
            load_h2v<F2>((const __half2*)(H + (size_t)i * D) + lane * F2, h);
            #pragma unroll
            for (int j = 0; j < F2; ++j) {
                float2 f = __half22float2(h[j]);
                acc[j].x = di * f.x; acc[j].y = di * f.y;
                acc2[j].x = 0.0f; acc2[j].y = 0.0f;
            }
        }
        int s0 = off[i], s1 = off[i + 1];
        for (int base = s0; base < s1; base += 32) {
            int nb = s1 - base; if (nb > 32) nb = 32;
            int sid = 0; float wv = 0.0f;
            if (lane < nb) { sid = srcs[base + lane]; wv = dinv[sid]; }
            int e = 0;
            for (; e + 1 < nb; e += 2) {
                int sa = __shfl_sync(0xFFFFFFFFu, sid, e);
                float wa = __shfl_sync(0xFFFFFFFFu, wv, e);
                int sb = __shfl_sync(0xFFFFFFFFu, sid, e + 1);
                float wb = __shfl_sync(0xFFFFFFFFu, wv, e + 1);
                __half2 ha[F2], hb[F2];
                load_h2v<F2>((const __half2*)(H + (size_t)sa * D) + lane * F2, ha);
                load_h2v<F2>((const __half2*)(H + (size_t)sb * D) + lane * F2, hb);
                #pragma unroll
                for (int j = 0; j < F2; ++j) {
                    float2 fa = __half22float2(ha[j]);
                    float2 fb = __half22float2(hb[j]);
                    acc[j].x  = fmaf(wa, fa.x, acc[j].x);
                    acc[j].y  = fmaf(wa, fa.y, acc[j].y);
                    acc2[j].x = fmaf(wb, fb.x, acc2[j].x);
                    acc2[j].y = fmaf(wb, fb.y, acc2[j].y);
                }
            }
            if (e < nb) {
                int sa = __shfl_sync(0xFFFFFFFFu, sid, e);
                float wa = __shfl_sync(0xFFFFFFFFu, wv, e);
                __half2 ha[F2];
                load_h2v<F2>((const __half2*)(H + (size_t)sa * D) + lane * F2, ha);
                #pragma unroll
                for (int j = 0; j < F2; ++j) {
                    float2 fa = __half22float2(ha[j]);
                    acc[j].x = fmaf(wa, fa.x, acc[j].x);
                    acc[j].y = fmaf(wa, fa.y, acc[j].y);
                }
            }
        }
        #pragma unroll
        for (int j = 0; j < F2; ++j) {
            float v0 = di * (acc[j].x + acc2[j].x);
            float v1 = di * (acc[j].y + acc2[j].y);
            if (bias) {
                v0 += bias[(lane * F2 + j) * 2];
                v1 += bias[(lane * F2 + j) * 2 + 1];
            }
            if (doRelu) { v0 = fmaxf(v0, 0.0f); v1 = fmaxf(v1, 0.0f); }
            vo[j].x = v0; vo[j].y = v1;
        }
    }
    __half2 oh[F2];
    #pragma unroll
    for (int j = 0; j < F2; ++j) oh[j] = __float22half2_rn(vo[j]);
    store_h2v<F2>((__half2*)(Oh + (size_t)i * D) + lane * F2, oh);
}

// ---------------- fused L4 agg + [64,2] GEMM ----------------
// H fp16 [N,64]; per node: aggregate, +b4+relu, then T[i,:] = h @ W5 (fp32).
__global__ __launch_bounds__(256) void agg64_gemm2_kernel(
    const __half* __restrict__ H,
    const int* __restrict__ off, const int* __restrict__ srcs,
    const float* __restrict__ dinv,
    const float* __restrict__ b4, const float* __restrict__ W5,
    float* __restrict__ T, int nTotal) {
    int lane = threadIdx.x & 31;
    int i = blockIdx.x * 8 + (threadIdx.x >> 5);
    if (i >= nTotal) return;
    float di = dinv[i];
    float2 f = __half22float2(*((const __half2*)(H + (size_t)i * 64) + lane));
    float a0 = di * f.x, a1 = di * f.y, c0 = 0.f, c1 = 0.f;
    int s0 = off[i], s1 = off[i + 1];
    for (int base = s0; base < s1; base += 32) {
        int nb = s1 - base; if (nb > 32) nb = 32;
        int sid = 0; float wv = 0.0f;
        if (lane < nb) { sid = srcs[base + lane]; wv = dinv[sid]; }
        int e = 0;
        for (; e + 1 < nb; e += 2) {
            int sa = __shfl_sync(0xFFFFFFFFu, sid, e);
            float wa = __shfl_sync(0xFFFFFFFFu, wv, e);
            int sb = __shfl_sync(0xFFFFFFFFu, sid, e + 1);
            float wb = __shfl_sync(0xFFFFFFFFu, wv, e + 1);
            float2 fa = __half22float2(*((const __half2*)(H + (size_t)sa * 64) + lane));
            float2 fb = __half22float2(*((const __half2*)(H + (size_t)sb * 64) + lane));
            a0 = fmaf(wa, fa.x, a0); a1 = fmaf(wa, fa.y, a1);
            c0 = fmaf(wb, fb.x, c0); c1 = fmaf(wb, fb.y, c1);
        }
        if (e < nb) {
            int sa = __shfl_sync(0xFFFFFFFFu, sid, e);
            float wa = __shfl_sync(0xFFFFFFFFu, wv, e);
            float2 fa = __half22float2(*((const __half2*)(H + (size_t)sa * 64) + lane));
            a0 = fmaf(wa, fa.x, a0); a1 = fmaf(wa, fa.y, a1);
        }
    }
    float v0 = di * (a0 + c0) + b4[lane * 2];
    float v1 = di * (a1 + c1) + b4[lane * 2 + 1];
    v0 = fmaxf(v0, 0.0f); v1 = fmaxf(v1, 0.0f);
    // T[i,c] = sum_k h[k] * W5[k*2+c], lane holds k = 2*lane, 2*lane+1
    float4 w = *(const float4*)(W5 + 4 * lane);
    float p0 = v0 * w.x + v1 * w.z;
    float p1 = v0 * w.y + v1 * w.w;
    #pragma unroll
    for (int o = 16; o > 0; o >>= 1) {
        p0 += __shfl_down_sync(0xFFFFFFFFu, p0, o);
        p1 += __shfl_down_sync(0xFFFFFFFFu, p1, o);
    }
    if (lane == 0) { T[2 * i] = p0; T[2 * i + 1] = p1; }
}

// ---------------- WMMA fp16 GEMM, 3-stage cp.async pipeline, fp16 out ----------------
template <int BN>
__global__ __launch_bounds__(256) void gemm_wmma_kernel(
    const __half* __restrict__ Ah, const __half* __restrict__ Bh,
    const float* __restrict__ bias, int doRelu,
    __half* __restrict__ Oh, int K, int N) {
    constexpr int A_LD = 40;            // 32 + 8 pad (halves)
    constexpr int B_LD = BN + 8;
    constexpr int A_BYTES = 128 * A_LD * 2;
    constexpr int STAGE = A_BYTES + 32 * B_LD * 2;
    constexpr int WN = BN / 2;
    constexpr int NF = WN / 16;

    extern __shared__ char sm[];
    int tid = threadIdx.x;
    int wid = tid >> 5;
    int mt = blockIdx.x, nt = blockIdx.y;
    int row0 = mt * 128, bn0 = nt * BN;
    int total = K >> 5;

    auto As = [&](int s) { return (__half*)(sm + s * STAGE); };
    auto Bs = [&](int s) { return (__half*)(sm + s * STAGE + A_BYTES); };

    auto issue = [&](int u) {
        int s = u % 3;
        int k0 = u << 5;
        #pragma unroll
        for (int c = 0; c < 2; ++c) {
            int chunk = tid + c * 256;
            int row = chunk >> 2, col8 = (chunk & 3) * 8;
            u32 dst = smem_u32(As(s) + row * A_LD + col8);
            cp_async16(dst, Ah + (size_t)(row0 + row) * K + k0 + col8);
        }
        constexpr int NCB = 32 * BN / 8 / 256;
        #pragma unroll
        for (int c = 0; c < NCB; ++c) {
            int chunk = tid + c * 256;
            int r = chunk / (BN / 8), c8 = (chunk % (BN / 8)) * 8;
            u32 dst = smem_u32(Bs(s) + r * B_LD + c8);
            cp_async16(dst, Bh + (size_t)(k0 + r) * N + bn0 + c8);
        }
        cp_commit();
    };

    int wm = (wid & 3) * 32;
    int wn = (wid >> 2) * WN;

    wmma::fragment<wmma::accumulator, 16, 16, 16, float> acc[2][NF];
    #pragma unroll
    for (int mi = 0; mi < 2; ++mi)
        #pragma unroll
        for (int ni = 0; ni < NF; ++ni) wmma::fill_fragment(acc[mi][ni], 0.0f);

    int issued = 0;
    for (int p = 0; p < 2 && issued < total; ++p) issue(issued++);
    for (int u = 0; u < total; ++u) {
        if (issued < total) issue(issued++);
        cp_wait_dyn(issued - u - 1);
        __syncthreads();
        int s = u % 3;
        const __half* a = As(s);
        const __half* b = Bs(s);
        #pragma unroll
        for (int kf = 0; kf < 2; ++kf) {
            wmma::fragment<wmma::matrix_a, 16, 16, 16, __half, wmma::row_major> af[2];
            wmma::fragment<wmma::matrix_b, 16, 16, 16, __half, wmma::row_major> bf[NF];
            #pragma unroll
            for (int mi = 0; mi < 2; ++mi)
                wmma::load_matrix_sync(af[mi], a + (wm + mi * 16) * A_LD + kf * 16, A_LD);
            #pragma unroll
            for (int ni = 0; ni < NF; ++ni)
                wmma::load_matrix_sync(bf[ni], b + (kf * 16) * B_LD + wn + ni * 16, B_LD);
            #pragma unroll
            for (int mi = 0; mi < 2; ++mi)
                #pragma unroll
                for (int ni = 0; ni < NF; ++ni)
                    wmma::mma_sync(acc[mi][ni], af[mi], bf[ni], acc[mi][ni]);
        }
        __syncthreads();
    }

    // epilogue via smem (fp32 tile), write fp16
    float* Cs = (float*)sm;
    #pragma unroll
    for (int mi = 0; mi < 2; ++mi)
        #pragma unroll
        for (int ni = 0; ni < NF; ++ni)
            wmma::store_matrix_sync(Cs + (wm + mi * 16) * BN + wn + ni * 16,
                                    acc[mi][ni], BN, wmma::mem_row_major);
    __syncthreads();

    for (int idx = tid; idx < 128 * BN; idx += 256) {
        int r = idx / BN, c = idx % BN;
        float v = Cs[idx];
        if (bias) v += bias[bn0 + c];
        if (doRelu) v = fmaxf(v, 0.0f);
        Oh[(size_t)(row0 + r) * N + bn0 + c] = __float2half(v);
    }
}

// ---------------- final aggregation (dim 2) + bias + log_softmax ----------------
__global__ void agg2_lsm_kernel(const float* __restrict__ T, const float* __restrict__ b,
                                float* __restrict__ out,
                                const int* __restrict__ off, const int* __restrict__ srcs,
                                const float* __restrict__ dinv, int n) {
    int i = blockIdx.x * blockDim.x + threadIdx.x;
    if (i >= n) return;
    float di = dinv[i];
    float a0 = di * T[2 * i];
    float a1 = di * T[2 * i + 1];
    int s0 = off[i], s1 = off[i + 1];
    for (int e = s0; e < s1; ++e) {
        int s = srcs[e];
        float w = dinv[s];
        a0 = fmaf(w, T[2 * s], a0);
        a1 = fmaf(w, T[2 * s + 1], a1);
    }
    float z0 = fmaf(di, a0, b[0]);
    float z1 = fmaf(di, a1, b[1]);
    float m = fmaxf(z0, z1);
    float lse = m + logf(expf(z0 - m) + expf(z1 - m));
    out[2 * i] = z0 - lse;
    out[2 * i + 1] = z1 - lse;
}

// ---------------- host launch ----------------
extern "C" void kernel_launch(void* const* d_in, const int* in_sizes, int n_in,
                              void* d_out, int out_size) {
    const float* x  = (const float*)d_in[0];
    const void*  ei = d_in[1];
    const float* W1 = (const float*)d_in[2];  const float* b1 = (const float*)d_in[3];
    const float* W2 = (const float*)d_in[4];  const float* b2 = (const float*)d_in[5];
    const float* W3 = (const float*)d_in[6];  const float* b3 = (const float*)d_in[7];
    const float* W4 = (const float*)d_in[8];  const float* b4 = (const float*)d_in[9];
    const float* W5 = (const float*)d_in[10]; const float* b5 = (const float*)d_in[11];
    float* out = (float*)d_out;

    const int N = N_NODES;
    const int E = N_EDGES;

    int *cnt, *off, *cur, *srcs, *bsum;
    float *dinv, *T;
    __half *h0, *h1, *xh, *bb1, *bb2, *bb3, *bb4;
    cudaGetSymbolAddress((void**)&cnt,  g_cnt);
    cudaGetSymbolAddress((void**)&off,  g_off);
    cudaGetSymbolAddress((void**)&cur,  g_cur);
    cudaGetSymbolAddress((void**)&srcs, g_srcs);
    cudaGetSymbolAddress((void**)&bsum, g_bsum);
    cudaGetSymbolAddress((void**)&dinv, g_dinv);
    cudaGetSymbolAddress((void**)&T,    g_T);
    cudaGetSymbolAddress((void**)&h0,   g_h0);
    cudaGetSymbolAddress((void**)&h1,   g_h1);
    cudaGetSymbolAddress((void**)&xh,   g_xh);
    cudaGetSymbolAddress((void**)&bb1,  g_b1);
    cudaGetSymbolAddress((void**)&bb2,  g_b2);
    cudaGetSymbolAddress((void**)&bb3,  g_b3);
    cudaGetSymbolAddress((void**)&bb4,  g_b4);

    const int STAGE128 = 128 * 40 * 2 + 32 * 136 * 2;  // 18944
    const int STAGE64  = 128 * 40 * 2 + 32 * 72 * 2;   // 14848
    const int SMEM128 = (3 * STAGE128 > 128 * 128 * 4) ? 3 * STAGE128 : 128 * 128 * 4;  // 65536
    const int SMEM64  = (3 * STAGE64 > 128 * 64 * 4) ? 3 * STAGE64 : 128 * 64 * 4;      // 44544
    cudaFuncSetAttribute(gemm_wmma_kernel<128>, cudaFuncAttributeMaxDynamicSharedMemorySize, SMEM128);
    cudaFuncSetAttribute(gemm_wmma_kernel<64>,  cudaFuncAttributeMaxDynamicSharedMemorySize, SMEM64);

    // ---- graph preprocessing + conversions ----
    detect_kernel<<<1, 32>>>(ei);
    zero_cnt_kernel<<<(N + 255) / 256, 256>>>(cnt, N);
    count_kernel<<<(E + 255) / 256, 256>>>(ei, cnt, E);
    decomp_all_kernel<<<(W1_SZ + W2_SZ + W3_SZ + W4_SZ + X_SZ + 255) / 256, 256>>>(
        W1, W2, W3, W4, x, bb1, bb2, bb3, bb4, xh);
    scan1_kernel<<<SCAN_NB, SCAN_BLK>>>(cnt, off, bsum, N);
    scan2_kernel<<<1, SCAN_BLK>>>(bsum, off, SCAN_NB, N);
    scan3_kernel<<<(N + 255) / 256, 256>>>(cnt, off, cur, dinv, bsum, N);
    fill_kernel<<<(E + 255) / 256, 256>>>(ei, cur, srcs, E);
    sortseg_kernel<<<(N + 255) / 256, 256>>>(off, srcs, N);

    const int AGG_BLKS = (PAD_ROWS + 7) / 8;  // 6272

    // L1: agg(xh, D=128) -> h0 ; gemm K=128 N=256 +b1+relu -> h1
    agg_h_kernel<128><<<AGG_BLKS, 256>>>(xh, off, srcs, dinv, nullptr, 0, PAD_ROWS, h0);
    gemm_wmma_kernel<128><<<dim3(MT_COUNT, 2), 256, SMEM128>>>(h0, bb1, b1, 1, h1, 128, 256);

    // L2: agg(h1, D=256) -> h0 ; gemm K=256 N=512 +b2+relu -> h1
    agg_h_kernel<256><<<AGG_BLKS, 256>>>(h1, off, srcs, dinv, nullptr, 0, PAD_ROWS, h0);
    gemm_wmma_kernel<128><<<dim3(MT_COUNT, 4), 256, SMEM128>>>(h0, bb2, b2, 1, h1, 256, 512);

    // L3: gemm K=512 N=256 -> h0 ; agg(+b3+relu) -> h1
    gemm_wmma_kernel<128><<<dim3(MT_COUNT, 2), 256, SMEM128>>>(h1, bb3, nullptr, 0, h0, 512, 256);
    agg_h_kernel<256><<<AGG_BLKS, 256>>>(h0, off, srcs, dinv, b3, 1, PAD_ROWS, h1);

    // L4: gemm K=256 N=64 -> h0 ; fused agg(+b4+relu) + [64,2] gemm -> T
    gemm_wmma_kernel<64><<<dim3(MT_COUNT, 1), 256, SMEM64>>>(h1, bb4, nullptr, 0, h0, 256, 64);
    agg64_gemm2_kernel<<<(N + 7) / 8, 256>>>(h0, off, srcs, dinv, b4, W5, T, N);

    // L5: agg(dim 2) + b5 + log_softmax -> out
    agg2_lsm_kernel<<<(N + 255) / 256, 256>>>(T, b5, out, off, srcs, dinv, N);
}

// round 10
// speedup vs baseline: 3.9701x; 1.0538x over previous
#include <cuda_runtime.h>
#include <cuda_fp16.h>
#include <mma.h>
#include <math.h>
#include <stdint.h>

using namespace nvcuda;

#define N_NODES 50000
#define N_EDGES 400000
#define MT_COUNT 392                 // padded row tiles: 392*128 = 50176
#define PAD_ROWS (MT_COUNT * 128)
#define SCAN_BLK 256
#define SCAN_NB ((N_NODES + SCAN_BLK - 1) / SCAN_BLK)

typedef unsigned int u32;
typedef unsigned long long u64;

// ---------------- scratch (static device globals; no allocs) ----------------
__device__ int   g_is64;
__device__ int   g_cnt[N_NODES];
__device__ int   g_off[N_NODES + 1];
__device__ int   g_cur[N_NODES];
__device__ int   g_srcs[N_EDGES];
__device__ int   g_bsum[SCAN_BLK];
__device__ float g_dinv[N_NODES];
__device__ float g_T[2 * N_NODES];
// fp16 activation ping-pong buffers, row-major [PAD_ROWS, <=512]
__device__ __half g_h0[(size_t)PAD_ROWS * 512];
__device__ __half g_h1[(size_t)PAD_ROWS * 512];
// x converted to fp16 [N_NODES,128]
__device__ __half g_xh[(size_t)N_NODES * 128];
// weights fp16
__device__ __half g_b1[128 * 256];
__device__ __half g_b2[256 * 512];
__device__ __half g_b3[512 * 256];
__device__ __half g_b4[256 * 64];

// ---------------- helpers ----------------
__device__ __forceinline__ u32 smem_u32(const void* p) {
    return (u32)__cvta_generic_to_shared(p);
}
__device__ __forceinline__ void cp_async16(u32 dst, const void* src) {
    asm volatile("cp.async.cg.shared.global [%0], [%1], 16;" :: "r"(dst), "l"(src));
}
__device__ __forceinline__ void cp_commit() {
    asm volatile("cp.async.commit_group;" ::: "memory");
}
__device__ __forceinline__ void cp_wait_dyn(int n) {
    if (n <= 0)      asm volatile("cp.async.wait_group 0;" ::: "memory");
    else if (n == 1) asm volatile("cp.async.wait_group 1;" ::: "memory");
    else             asm volatile("cp.async.wait_group 2;" ::: "memory");
}
template <int F2>
__device__ __forceinline__ void load_h2v(const __half2* p, __half2* v) {
    if (F2 == 1)      *(u32*)v  = *(const u32*)p;
    else if (F2 == 2) *(uint2*)v = *(const uint2*)p;
    else              *(uint4*)v = *(const uint4*)p;
}
template <int F2>
__device__ __forceinline__ void store_h2v(__half2* p, const __half2* v) {
    if (F2 == 1)      *(u32*)p  = *(const u32*)v;
    else if (F2 == 2) *(uint2*)p = *(const uint2*)v;
    else              *(uint4*)p = *(const uint4*)v;
}

// ---------------- edge dtype detection (warp-parallel) ----------------
__global__ void detect_kernel(const void* eiv) {
    const long long* p = (const long long*)eiv;
    int t = threadIdx.x;
    int bad = 0;
    #pragma unroll
    for (int e = t; e < 256; e += 32) {
        long long v = p[e];
        if (v < 0 || v >= N_NODES) bad = 1;
    }
    unsigned m = __ballot_sync(0xFFFFFFFFu, bad);
    if (t == 0) g_is64 = (m == 0u);
}
__device__ __forceinline__ int load_src(const void* eiv, int E, int e) {
    return g_is64 ? (int)((const long long*)eiv)[e] : ((const int*)eiv)[e];
}
__device__ __forceinline__ int load_dst(const void* eiv, int E, int e) {
    return g_is64 ? (int)((const long long*)eiv)[E + e] : ((const int*)eiv)[E + e];
}

// ---------------- preprocessing ----------------
__global__ void zero_cnt_kernel(int* cnt, int n) {
    int i = blockIdx.x * blockDim.x + threadIdx.x;
    if (i < n) cnt[i] = 0;
}
__global__ void count_kernel(const void* __restrict__ eiv, int* cnt, int E) {
    int e = blockIdx.x * blockDim.x + threadIdx.x;
    if (e < E) atomicAdd(&cnt[load_dst(eiv, E, e)], 1);
}
__global__ void scan1_kernel(const int* __restrict__ cnt, int* __restrict__ off,
                             int* __restrict__ bsum, int n) {
    __shared__ int sh[SCAN_BLK];
    int t = threadIdx.x;
    int i = blockIdx.x * SCAN_BLK + t;
    int v = (i < n) ? cnt[i] : 0;
    sh[t] = v;
    __syncthreads();
    for (int d = 1; d < SCAN_BLK; d <<= 1) {
        int x = 0;
        if (t >= d) x = sh[t - d];
        __syncthreads();
        if (t >= d) sh[t] += x;
        __syncthreads();
    }
    if (i < n) off[i] = sh[t] - v;
    if (t == SCAN_BLK - 1) bsum[blockIdx.x] = sh[t];
}
__global__ void scan2_kernel(int* __restrict__ bsum, int* __restrict__ off, int nb, int n) {
    __shared__ int sh[SCAN_BLK];
    int t = threadIdx.x;
    int v = (t < nb) ? bsum[t] : 0;
    sh[t] = v;
    __syncthreads();
    for (int d = 1; d < SCAN_BLK; d <<= 1) {
        int x = 0;
        if (t >= d) x = sh[t - d];
        __syncthreads();
        if (t >= d) sh[t] += x;
        __syncthreads();
    }
    if (t < nb) bsum[t] = sh[t] - v;
    if (t == nb - 1) off[n] = sh[t];
}
__global__ void scan3_kernel(const int* __restrict__ cnt, int* __restrict__ off,
                             int* __restrict__ cur, float* __restrict__ dinv,
                             const int* __restrict__ bsum, int n) {
    int i = blockIdx.x * blockDim.x + threadIdx.x;
    if (i < n) {
        int o = off[i] + bsum[i >> 8];
        off[i] = o;
        cur[i] = o;
        dinv[i] = rsqrtf((float)(cnt[i] + 1));
    }
}
__global__ void fill_kernel(const void* __restrict__ eiv, int* cur,
                            int* __restrict__ srcs, int E) {
    int e = blockIdx.x * blockDim.x + threadIdx.x;
    if (e < E) {
        int d = load_dst(eiv, E, e);
        int pos = atomicAdd(&cur[d], 1);
        srcs[pos] = load_src(eiv, E, e);
    }
}
__global__ void sortseg_kernel(const int* __restrict__ off, int* __restrict__ srcs, int n) {
    int i = blockIdx.x * blockDim.x + threadIdx.x;
    if (i >= n) return;
    int s0 = off[i], s1 = off[i + 1];
    for (int a = s0 + 1; a < s1; ++a) {
        int key = srcs[a];
        int b = a - 1;
        while (b >= s0 && srcs[b] > key) { srcs[b + 1] = srcs[b]; --b; }
        srcs[b + 1] = key;
    }
}

// ---------------- fused vectorized conversion: W1..W4 and x -> fp16 ----------------
// 4 floats per thread (float4 load, 2x half2 store).
#define W1_SZ (128 * 256)
#define W2_SZ (256 * 512)
#define W3_SZ (512 * 256)
#define W4_SZ (256 * 64)
#define X_SZ  (N_NODES * 128)
#define CONV_TOTAL4 ((W1_SZ + W2_SZ + W3_SZ + W4_SZ + X_SZ) / 4)
__device__ __forceinline__ void conv4(const float* __restrict__ S, __half* __restrict__ D, int e4) {
    float4 v = *(const float4*)(S + 4 * e4);
    __half2 p0; p0.x = __float2half(v.x); p0.y = __float2half(v.y);
    __half2 p1; p1.x = __float2half(v.z); p1.y = __float2half(v.w);
    *(__half2*)(D + 4 * e4) = p0;
    *(__half2*)(D + 4 * e4 + 2) = p1;
}
__global__ void decomp_all_kernel(const float* __restrict__ W1, const float* __restrict__ W2,
                                  const float* __restrict__ W3, const float* __restrict__ W4,
                                  const float* __restrict__ X,
                                  __half* __restrict__ B1, __half* __restrict__ B2,
                                  __half* __restrict__ B3, __half* __restrict__ B4,
                                  __half* __restrict__ XH) {
    int e = blockIdx.x * blockDim.x + threadIdx.x;
    if (e < W1_SZ / 4) { conv4(W1, B1, e); return; }
    e -= W1_SZ / 4;
    if (e < W2_SZ / 4) { conv4(W2, B2, e); return; }
    e -= W2_SZ / 4;
    if (e < W3_SZ / 4) { conv4(W3, B3, e); return; }
    e -= W3_SZ / 4;
    if (e < W4_SZ / 4) { conv4(W4, B4, e); return; }
    e -= W4_SZ / 4;
    if (e < X_SZ / 4) conv4(X, XH, e);
}

// ---------------- aggregation (fp16 in, fp16 out, fp32 accumulate) ----------------
// out[i] = dinv[i]*(dinv[i]*h[i] + sum dinv[s]*h[s]) (+bias, relu)
// Warp per node, 8 warps/block, no smem/barriers. Lane handles F2 half2's.
template <int D>
__global__ __launch_bounds__(256) void agg_h_kernel(
    const __half* __restrict__ H,
    const int* __restrict__ off, const int* __restrict__ srcs,
    const float* __restrict__ dinv,
    const float* __restrict__ bias, int doRelu, int nTotal,
    __half* __restrict__ Oh) {
    constexpr int F2 = D / 64;          // half2 per lane
    int lane = threadIdx.x & 31;
    int i = blockIdx.x * 8 + (threadIdx.x >> 5);
    if (i >= nTotal) return;

    float2 vo[F2];
    #pragma unroll
    for (int j = 0; j < F2; ++j) { vo[j].x = 0.0f; vo[j].y = 0.0f; }

    if (i < N_NODES) {
        float di = dinv[i];
        float2 acc[F2], acc2[F2];
        {
            __half2 h[F2];
            load_h2v<F2>((const __half2*)(H + (size_t)i * D) + lane * F2, h);
            #pragma unroll
            for (int j = 0; j < F2; ++j) {
                float2 f = __half22float2(h[j]);
                acc[j].x = di * f.x; acc[j].y = di * f.y;
                acc2[j].x = 0.0f; acc2[j].y = 0.0f;
            }
        }
        int s0 = off[i], s1 = off[i + 1];
        for (int base = s0; base < s1; base += 32) {
            int nb = s1 - base; if (nb > 32) nb = 32;
            int sid = 0; float wv = 0.0f;
            if (lane < nb) { sid = srcs[base + lane]; wv = dinv[sid]; }
            int e = 0;
            for (; e + 1 < nb; e += 2) {
                int sa = __shfl_sync(0xFFFFFFFFu, sid, e);
                float wa = __shfl_sync(0xFFFFFFFFu, wv, e);
                int sb = __shfl_sync(0xFFFFFFFFu, sid, e + 1);
                float wb = __shfl_sync(0xFFFFFFFFu, wv, e + 1);
                __half2 ha[F2], hb[F2];
                load_h2v<F2>((const __half2*)(H + (size_t)sa * D) + lane * F2, ha);
                load_h2v<F2>((const __half2*)(H + (size_t)sb * D) + lane * F2, hb);
                #pragma unroll
                for (int j = 0; j < F2; ++j) {
                    float2 fa = __half22float2(ha[j]);
                    float2 fb = __half22float2(hb[j]);
                    acc[j].x  = fmaf(wa, fa.x, acc[j].x);
                    acc[j].y  = fmaf(wa, fa.y, acc[j].y);
                    acc2[j].x = fmaf(wb, fb.x, acc2[j].x);
                    acc2[j].y = fmaf(wb, fb.y, acc2[j].y);
                }
            }
            if (e < nb) {
                int sa = __shfl_sync(0xFFFFFFFFu, sid, e);
                float wa = __shfl_sync(0xFFFFFFFFu, wv, e);
                __half2 ha[F2];
                load_h2v<F2>((const __half2*)(H + (size_t)sa * D) + lane * F2, ha);
                #pragma unroll
                for (int j = 0; j < F2; ++j) {
                    float2 fa = __half22float2(ha[j]);
                    acc[j].x = fmaf(wa, fa.x, acc[j].x);
                    acc[j].y = fmaf(wa, fa.y, acc[j].y);
                }
            }
        }
        #pragma unroll
        for (int j = 0; j < F2; ++j) {
            float v0 = di * (acc[j].x + acc2[j].x);
            float v1 = di * (acc[j].y + acc2[j].y);
            if (bias) {
                v0 += bias[(lane * F2 + j) * 2];
                v1 += bias[(lane * F2 + j) * 2 + 1];
            }
            if (doRelu) { v0 = fmaxf(v0, 0.0f); v1 = fmaxf(v1, 0.0f); }
            vo[j].x = v0; vo[j].y = v1;
        }
    }
    __half2 oh[F2];
    #pragma unroll
    for (int j = 0; j < F2; ++j) oh[j] = __float22half2_rn(vo[j]);
    store_h2v<F2>((__half2*)(Oh + (size_t)i * D) + lane * F2, oh);
}

// ---------------- fused L4 agg + [64,2] GEMM ----------------
__global__ __launch_bounds__(256) void agg64_gemm2_kernel(
    const __half* __restrict__ H,
    const int* __restrict__ off, const int* __restrict__ srcs,
    const float* __restrict__ dinv,
    const float* __restrict__ b4, const float* __restrict__ W5,
    float* __restrict__ T, int nTotal) {
    int lane = threadIdx.x & 31;
    int i = blockIdx.x * 8 + (threadIdx.x >> 5);
    if (i >= nTotal) return;
    float di = dinv[i];
    float2 f = __half22float2(*((const __half2*)(H + (size_t)i * 64) + lane));
    float a0 = di * f.x, a1 = di * f.y, c0 = 0.f, c1 = 0.f;
    int s0 = off[i], s1 = off[i + 1];
    for (int base = s0; base < s1; base += 32) {
        int nb = s1 - base; if (nb > 32) nb = 32;
        int sid = 0; float wv = 0.0f;
        if (lane < nb) { sid = srcs[base + lane]; wv = dinv[sid]; }
        int e = 0;
        for (; e + 1 < nb; e += 2) {
            int sa = __shfl_sync(0xFFFFFFFFu, sid, e);
            float wa = __shfl_sync(0xFFFFFFFFu, wv, e);
            int sb = __shfl_sync(0xFFFFFFFFu, sid, e + 1);
            float wb = __shfl_sync(0xFFFFFFFFu, wv, e + 1);
            float2 fa = __half22float2(*((const __half2*)(H + (size_t)sa * 64) + lane));
            float2 fb = __half22float2(*((const __half2*)(H + (size_t)sb * 64) + lane));
            a0 = fmaf(wa, fa.x, a0); a1 = fmaf(wa, fa.y, a1);
            c0 = fmaf(wb, fb.x, c0); c1 = fmaf(wb, fb.y, c1);
        }
        if (e < nb) {
            int sa = __shfl_sync(0xFFFFFFFFu, sid, e);
            float wa = __shfl_sync(0xFFFFFFFFu, wv, e);
            float2 fa = __half22float2(*((const __half2*)(H + (size_t)sa * 64) + lane));
            a0 = fmaf(wa, fa.x, a0); a1 = fmaf(wa, fa.y, a1);
        }
    }
    float v0 = di * (a0 + c0) + b4[lane * 2];
    float v1 = di * (a1 + c1) + b4[lane * 2 + 1];
    v0 = fmaxf(v0, 0.0f); v1 = fmaxf(v1, 0.0f);
    float4 w = *(const float4*)(W5 + 4 * lane);
    float p0 = v0 * w.x + v1 * w.z;
    float p1 = v0 * w.y + v1 * w.w;
    #pragma unroll
    for (int o = 16; o > 0; o >>= 1) {
        p0 += __shfl_down_sync(0xFFFFFFFFu, p0, o);
        p1 += __shfl_down_sync(0xFFFFFFFFu, p1, o);
    }
    if (lane == 0) { T[2 * i] = p0; T[2 * i + 1] = p1; }
}

// ---------------- WMMA fp16 GEMM, 3-stage pipeline, single sync per k-step ----------------
template <int BN>
__global__ __launch_bounds__(256) void gemm_wmma_kernel(
    const __half* __restrict__ Ah, const __half* __restrict__ Bh,
    const float* __restrict__ bias, int doRelu,
    __half* __restrict__ Oh, int K, int N) {
    constexpr int A_LD = 40;            // 32 + 8 pad (halves)
    constexpr int B_LD = BN + 8;
    constexpr int A_BYTES = 128 * A_LD * 2;
    constexpr int STAGE = A_BYTES + 32 * B_LD * 2;
    constexpr int WN = BN / 2;
    constexpr int NF = WN / 16;

    extern __shared__ char sm[];
    int tid = threadIdx.x;
    int wid = tid >> 5;
    int mt = blockIdx.x, nt = blockIdx.y;
    int row0 = mt * 128, bn0 = nt * BN;
    int total = K >> 5;

    auto As = [&](int s) { return (__half*)(sm + s * STAGE); };
    auto Bs = [&](int s) { return (__half*)(sm + s * STAGE + A_BYTES); };

    auto issue = [&](int u) {
        int s = u % 3;
        int k0 = u << 5;
        #pragma unroll
        for (int c = 0; c < 2; ++c) {
            int chunk = tid + c * 256;
            int row = chunk >> 2, col8 = (chunk & 3) * 8;
            u32 dst = smem_u32(As(s) + row * A_LD + col8);
            cp_async16(dst, Ah + (size_t)(row0 + row) * K + k0 + col8);
        }
        constexpr int NCB = 32 * BN / 8 / 256;
        #pragma unroll
        for (int c = 0; c < NCB; ++c) {
            int chunk = tid + c * 256;
            int r = chunk / (BN / 8), c8 = (chunk % (BN / 8)) * 8;
            u32 dst = smem_u32(Bs(s) + r * B_LD + c8);
            cp_async16(dst, Bh + (size_t)(k0 + r) * N + bn0 + c8);
        }
        cp_commit();
    };

    int wm = (wid & 3) * 32;
    int wn = (wid >> 2) * WN;

    wmma::fragment<wmma::accumulator, 16, 16, 16, float> acc[2][NF];
    #pragma unroll
    for (int mi = 0; mi < 2; ++mi)
        #pragma unroll
        for (int ni = 0; ni < NF; ++ni) wmma::fill_fragment(acc[mi][ni], 0.0f);

    int issued = 0;
    for (int p = 0; p < 2 && issued < total; ++p) issue(issued++);
    for (int u = 0; u < total; ++u) {
        cp_wait_dyn(issued - u - 1);
        // Single barrier: proves (a) stage u's data visible to all threads and
        // (b) every thread finished computing stage u-1 == ring slot (u+2)%3,
        // so issuing into that slot below is race-free.
        __syncthreads();
        if (issued < total) issue(issued++);
        int s = u % 3;
        const __half* a = As(s);
        const __half* b = Bs(s);
        #pragma unroll
        for (int kf = 0; kf < 2; ++kf) {
            wmma::fragment<wmma::matrix_a, 16, 16, 16, __half, wmma::row_major> af[2];
            wmma::fragment<wmma::matrix_b, 16, 16, 16, __half, wmma::row_major> bf[NF];
            #pragma unroll
            for (int mi = 0; mi < 2; ++mi)
                wmma::load_matrix_sync(af[mi], a + (wm + mi * 16) * A_LD + kf * 16, A_LD);
            #pragma unroll
            for (int ni = 0; ni < NF; ++ni)
                wmma::load_matrix_sync(bf[ni], b + (kf * 16) * B_LD + wn + ni * 16, B_LD);
            #pragma unroll
            for (int mi = 0; mi < 2; ++mi)
                #pragma unroll
                for (int ni = 0; ni < NF; ++ni)
                    wmma::mma_sync(acc[mi][ni], af[mi], bf[ni], acc[mi][ni]);
        }
    }
    __syncthreads();  // protect epilogue smem reuse against lagging stage reads

    // epilogue via smem (fp32 tile), write fp16 vectorized
    float* Cs = (float*)sm;
    #pragma unroll
    for (int mi = 0; mi < 2; ++mi)
        #pragma unroll
        for (int ni = 0; ni < NF; ++ni)
            wmma::store_matrix_sync(Cs + (wm + mi * 16) * BN + wn + ni * 16,
                                    acc[mi][ni], BN, wmma::mem_row_major);
    __syncthreads();

    for (int idx2 = tid; idx2 < 128 * BN / 2; idx2 += 256) {
        int r = idx2 / (BN / 2), c2 = idx2 % (BN / 2);
        float v0 = Cs[r * BN + 2 * c2];
        float v1 = Cs[r * BN + 2 * c2 + 1];
        if (bias) { v0 += bias[bn0 + 2 * c2]; v1 += bias[bn0 + 2 * c2 + 1]; }
        if (doRelu) { v0 = fmaxf(v0, 0.0f); v1 = fmaxf(v1, 0.0f); }
        __half2 p; p.x = __float2half(v0); p.y = __float2half(v1);
        *(__half2*)(Oh + (size_t)(row0 + r) * N + bn0 + 2 * c2) = p;
    }
}

// ---------------- final aggregation (dim 2) + bias + log_softmax ----------------
__global__ void agg2_lsm_kernel(const float* __restrict__ T, const float* __restrict__ b,
                                float* __restrict__ out,
                                const int* __restrict__ off, const int* __restrict__ srcs,
                                const float* __restrict__ dinv, int n) {
    int i = blockIdx.x * blockDim.x + threadIdx.x;
    if (i >= n) return;
    float di = dinv[i];
    float a0 = di * T[2 * i];
    float a1 = di * T[2 * i + 1];
    int s0 = off[i], s1 = off[i + 1];
    for (int e = s0; e < s1; ++e) {
        int s = srcs[e];
        float w = dinv[s];
        a0 = fmaf(w, T[2 * s], a0);
        a1 = fmaf(w, T[2 * s + 1], a1);
    }
    float z0 = fmaf(di, a0, b[0]);
    float z1 = fmaf(di, a1, b[1]);
    float m = fmaxf(z0, z1);
    float lse = m + logf(expf(z0 - m) + expf(z1 - m));
    out[2 * i] = z0 - lse;
    out[2 * i + 1] = z1 - lse;
}

// ---------------- host launch ----------------
extern "C" void kernel_launch(void* const* d_in, const int* in_sizes, int n_in,
                              void* d_out, int out_size) {
    const float* x  = (const float*)d_in[0];
    const void*  ei = d_in[1];
    const float* W1 = (const float*)d_in[2];  const float* b1 = (const float*)d_in[3];
    const float* W2 = (const float*)d_in[4];  const float* b2 = (const float*)d_in[5];
    const float* W3 = (const float*)d_in[6];  const float* b3 = (const float*)d_in[7];
    const float* W4 = (const float*)d_in[8];  const float* b4 = (const float*)d_in[9];
    const float* W5 = (const float*)d_in[10]; const float* b5 = (const float*)d_in[11];
    float* out = (float*)d_out;

    const int N = N_NODES;
    const int E = N_EDGES;

    int *cnt, *off, *cur, *srcs, *bsum;
    float *dinv, *T;
    __half *h0, *h1, *xh, *bb1, *bb2, *bb3, *bb4;
    cudaGetSymbolAddress((void**)&cnt,  g_cnt);
    cudaGetSymbolAddress((void**)&off,  g_off);
    cudaGetSymbolAddress((void**)&cur,  g_cur);
    cudaGetSymbolAddress((void**)&srcs, g_srcs);
    cudaGetSymbolAddress((void**)&bsum, g_bsum);
    cudaGetSymbolAddress((void**)&dinv, g_dinv);
    cudaGetSymbolAddress((void**)&T,    g_T);
    cudaGetSymbolAddress((void**)&h0,   g_h0);
    cudaGetSymbolAddress((void**)&h1,   g_h1);
    cudaGetSymbolAddress((void**)&xh,   g_xh);
    cudaGetSymbolAddress((void**)&bb1,  g_b1);
    cudaGetSymbolAddress((void**)&bb2,  g_b2);
    cudaGetSymbolAddress((void**)&bb3,  g_b3);
    cudaGetSymbolAddress((void**)&bb4,  g_b4);

    const int STAGE128 = 128 * 40 * 2 + 32 * 136 * 2;  // 18944
    const int STAGE64  = 128 * 40 * 2 + 32 * 72 * 2;   // 14848
    const int SMEM128 = (3 * STAGE128 > 128 * 128 * 4) ? 3 * STAGE128 : 128 * 128 * 4;  // 65536
    const int SMEM64  = (3 * STAGE64 > 128 * 64 * 4) ? 3 * STAGE64 : 128 * 64 * 4;      // 44544
    cudaFuncSetAttribute(gemm_wmma_kernel<128>, cudaFuncAttributeMaxDynamicSharedMemorySize, SMEM128);
    cudaFuncSetAttribute(gemm_wmma_kernel<64>,  cudaFuncAttributeMaxDynamicSharedMemorySize, SMEM64);

    // ---- graph preprocessing + conversions ----
    detect_kernel<<<1, 32>>>(ei);
    zero_cnt_kernel<<<(N + 255) / 256, 256>>>(cnt, N);
    count_kernel<<<(E + 255) / 256, 256>>>(ei, cnt, E);
    decomp_all_kernel<<<(CONV_TOTAL4 + 255) / 256, 256>>>(
        W1, W2, W3, W4, x, bb1, bb2, bb3, bb4, xh);
    scan1_kernel<<<SCAN_NB, SCAN_BLK>>>(cnt, off, bsum, N);
    scan2_kernel<<<1, SCAN_BLK>>>(bsum, off, SCAN_NB, N);
    scan3_kernel<<<(N + 255) / 256, 256>>>(cnt, off, cur, dinv, bsum, N);
    fill_kernel<<<(E + 255) / 256, 256>>>(ei, cur, srcs, E);
    sortseg_kernel<<<(N + 255) / 256, 256>>>(off, srcs, N);

    const int AGG_BLKS = (PAD_ROWS + 7) / 8;  // 6272

    // L1: agg(xh, D=128) -> h0 ; gemm K=128 N=256 +b1+relu -> h1
    agg_h_kernel<128><<<AGG_BLKS, 256>>>(xh, off, srcs, dinv, nullptr, 0, PAD_ROWS, h0);
    gemm_wmma_kernel<128><<<dim3(MT_COUNT, 2), 256, SMEM128>>>(h0, bb1, b1, 1, h1, 128, 256);

    // L2: agg(h1, D=256) -> h0 ; gemm K=256 N=512 +b2+relu -> h1
    agg_h_kernel<256><<<AGG_BLKS, 256>>>(h1, off, srcs, dinv, nullptr, 0, PAD_ROWS, h0);
    gemm_wmma_kernel<128><<<dim3(MT_COUNT, 4), 256, SMEM128>>>(h0, bb2, b2, 1, h1, 256, 512);

    // L3: gemm K=512 N=256 -> h0 ; agg(+b3+relu) -> h1
    gemm_wmma_kernel<128><<<dim3(MT_COUNT, 2), 256, SMEM128>>>(h1, bb3, nullptr, 0, h0, 512, 256);
    agg_h_kernel<256><<<AGG_BLKS, 256>>>(h0, off, srcs, dinv, b3, 1, PAD_ROWS, h1);

    // L4: gemm K=256 N=64 -> h0 ; fused agg(+b4+relu) + [64,2] gemm -> T
    gemm_wmma_kernel<64><<<dim3(MT_COUNT, 1), 256, SMEM64>>>(h1, bb4, nullptr, 0, h0, 256, 64);
    agg64_gemm2_kernel<<<(N + 7) / 8, 256>>>(h0, off, srcs, dinv, b4, W5, T, N);

    // L5: agg(dim 2) + b5 + log_softmax -> out
    agg2_lsm_kernel<<<(N + 255) / 256, 256>>>(T, b5, out, off, srcs, dinv, N);
}